// round 1
// baseline (speedup 1.0000x reference)
#include <cuda_runtime.h>
#include <math.h>
#include <stdint.h>

// Problem constants
constexpr int T_ = 128, B_ = 32, L_ = 2, H_ = 1024, E_ = 1024, V_ = 32000;
constexpr int TB  = T_ * B_;     // 4096
constexpr int G4H = 4 * H_;      // 4096

// Scratch (device globals: allocation-free rule)
__device__ float g_xb0[TB * E_];       // embed out / layer1 out
__device__ float g_xb1[TB * H_];       // layer0 out
__device__ float g_xproj[TB * G4H];    // per-layer input projection
__device__ float g_c[B_ * H_];         // running cell state

// ---------------------------------------------------------------------------
// Embedding gather: out[tb, :] = emb[idx[tb], :]   (E = 1024 -> 256 float4)
// ---------------------------------------------------------------------------
__global__ void embed_kernel(const int* __restrict__ idx,
                             const float* __restrict__ emb,
                             float* __restrict__ out) {
    int tb = blockIdx.x;
    int v  = idx[tb];
    const float4* src = (const float4*)(emb + (size_t)v * E_);
    float4*       dst = (float4*)(out + (size_t)tb * E_);
    dst[threadIdx.x] = src[threadIdx.x];
}

// ---------------------------------------------------------------------------
// fp32 GEMM: C[M,N] = A[M,K] @ B[N,K]^T + bias1[n] + bias2[n]
// Both A and B are K-contiguous (row-major). BM=BN=128, BK=16, 256 threads,
// 8x8 per thread. All problem shapes divide tiles exactly -> no predication.
// ---------------------------------------------------------------------------
constexpr int BM = 128, BN = 128, BK = 16;

__global__ __launch_bounds__(256)
void gemm_nt_bias(const float* __restrict__ A, const float* __restrict__ B,
                  const float* __restrict__ bias1, const float* __restrict__ bias2,
                  float* __restrict__ C, int M, int N, int K, int ldc) {
    __shared__ float As[BK][BM + 4];
    __shared__ float Bs[BK][BN + 4];

    const int bx = blockIdx.x;   // N tile
    const int by = blockIdx.y;   // M tile
    const int tid = threadIdx.x;
    const int tcol = tid & 15;   // 0..15
    const int trow = tid >> 4;   // 0..15

    const float* Ag = A + (size_t)by * BM * K;
    const float* Bg = B + (size_t)bx * BN * K;

    float acc[8][8];
#pragma unroll
    for (int i = 0; i < 8; i++)
#pragma unroll
        for (int j = 0; j < 8; j++) acc[i][j] = 0.f;

    for (int kt = 0; kt < K; kt += BK) {
        // load 128x16 tiles (512 float4 each), 2 float4 per thread per matrix
#pragma unroll
        for (int ld = 0; ld < 2; ld++) {
            int id  = tid + ld * 256;
            int row = id >> 2;
            int c4  = (id & 3) * 4;
            float4 av = *(const float4*)(Ag + (size_t)row * K + kt + c4);
            As[c4 + 0][row] = av.x; As[c4 + 1][row] = av.y;
            As[c4 + 2][row] = av.z; As[c4 + 3][row] = av.w;
            float4 bv = *(const float4*)(Bg + (size_t)row * K + kt + c4);
            Bs[c4 + 0][row] = bv.x; Bs[c4 + 1][row] = bv.y;
            Bs[c4 + 2][row] = bv.z; Bs[c4 + 3][row] = bv.w;
        }
        __syncthreads();

#pragma unroll
        for (int k = 0; k < BK; k++) {
            float4 a0 = *(const float4*)&As[k][trow * 8];
            float4 a1 = *(const float4*)&As[k][trow * 8 + 4];
            float4 b0 = *(const float4*)&Bs[k][tcol * 8];
            float4 b1 = *(const float4*)&Bs[k][tcol * 8 + 4];
            float ar[8] = {a0.x, a0.y, a0.z, a0.w, a1.x, a1.y, a1.z, a1.w};
            float br[8] = {b0.x, b0.y, b0.z, b0.w, b1.x, b1.y, b1.z, b1.w};
#pragma unroll
            for (int i = 0; i < 8; i++)
#pragma unroll
                for (int j = 0; j < 8; j++) acc[i][j] += ar[i] * br[j];
        }
        __syncthreads();
    }

    const int cn = bx * BN + tcol * 8;
    float bsum[8];
#pragma unroll
    for (int j = 0; j < 8; j++) {
        float bb = bias1 ? bias1[cn + j] : 0.f;
        if (bias2) bb += bias2[cn + j];
        bsum[j] = bb;
    }
#pragma unroll
    for (int i = 0; i < 8; i++) {
        size_t row = (size_t)(by * BM + trow * 8 + i);
        float4 o0, o1;
        o0.x = acc[i][0] + bsum[0]; o0.y = acc[i][1] + bsum[1];
        o0.z = acc[i][2] + bsum[2]; o0.w = acc[i][3] + bsum[3];
        o1.x = acc[i][4] + bsum[4]; o1.y = acc[i][5] + bsum[5];
        o1.z = acc[i][6] + bsum[6]; o1.w = acc[i][7] + bsum[7];
        *(float4*)(C + row * ldc + cn)     = o0;
        *(float4*)(C + row * ldc + cn + 4) = o1;
    }
}

// ---------------------------------------------------------------------------
// Fused LSTM step: gates = xproj[t] + h_prev @ W_hh^T ; apply nonlinearities.
// Block owns UN=8 hidden units -> 32 W_hh rows (4 gates x 8 units), all 32
// batches. h_prev is read from y[t-1] (or h0); h_out is y[t] -> no races.
// c is block-exclusive (single buffer g_c).
// ---------------------------------------------------------------------------
constexpr int UN = 8;
constexpr int KC = 128;

__device__ __forceinline__ float sigf(float x) { return 1.f / (1.f + expf(-x)); }

__global__ __launch_bounds__(256)
void lstm_step(const float* __restrict__ xproj_t,   // [B, 4H] for this t
               const float* __restrict__ Whh,       // [4H, H]
               const float* __restrict__ h_prev,    // [B, H]
               const float* __restrict__ c_prev,    // [B, H]
               float* __restrict__ c_out,           // g_c [B, H]
               float* __restrict__ h_out) {         // y + t*B*H
    __shared__ float sh[32][KC + 4];
    __shared__ float sw[32][KC + 4];
    __shared__ float sg[32][33];   // gates [b][r]

    const int tid = threadIdx.x;
    const int n0  = blockIdx.x * UN;
    const int r   = tid & 31;     // W-row within block (gate*8 + uu)
    const int bg  = tid >> 5;     // 0..7

    float acc0 = 0.f, acc1 = 0.f, acc2 = 0.f, acc3 = 0.f;

    for (int k0 = 0; k0 < H_; k0 += KC) {
        // cooperative loads: 32 rows x 128 floats for both h and W tiles
#pragma unroll
        for (int ld = 0; ld < 4; ld++) {
            int id = tid + ld * 256;
            int rr = id >> 5;          // 0..31
            int k4 = (id & 31) * 4;
            *(float4*)&sh[rr][k4] =
                *(const float4*)(h_prev + (size_t)rr * H_ + k0 + k4);
            int gr = (rr >> 3) * H_ + n0 + (rr & 7);   // gate*H + unit
            *(float4*)&sw[rr][k4] =
                *(const float4*)(Whh + (size_t)gr * H_ + k0 + k4);
        }
        __syncthreads();

#pragma unroll
        for (int k = 0; k < KC; k += 4) {
            float4 w  = *(const float4*)&sw[r][k];
            float4 hA = *(const float4*)&sh[bg][k];
            float4 hB = *(const float4*)&sh[bg + 8][k];
            float4 hC = *(const float4*)&sh[bg + 16][k];
            float4 hD = *(const float4*)&sh[bg + 24][k];
            acc0 += w.x * hA.x + w.y * hA.y + w.z * hA.z + w.w * hA.w;
            acc1 += w.x * hB.x + w.y * hB.y + w.z * hB.z + w.w * hB.w;
            acc2 += w.x * hC.x + w.y * hC.y + w.z * hC.z + w.w * hC.w;
            acc3 += w.x * hD.x + w.y * hD.y + w.z * hD.z + w.w * hD.w;
        }
        __syncthreads();
    }

    sg[bg][r]      = acc0;
    sg[bg + 8][r]  = acc1;
    sg[bg + 16][r] = acc2;
    sg[bg + 24][r] = acc3;
    __syncthreads();

    // phase 2: one thread per (b, unit): b = tid/8, uu = tid%8
    const int b  = tid >> 3;
    const int uu = tid & 7;
    const int u  = n0 + uu;
    const float* xp = xproj_t + (size_t)b * G4H;

    float gi = sg[b][0 * 8 + uu] + xp[0 * H_ + u];
    float gf = sg[b][1 * 8 + uu] + xp[1 * H_ + u];
    float gg = sg[b][2 * 8 + uu] + xp[2 * H_ + u];
    float go = sg[b][3 * 8 + uu] + xp[3 * H_ + u];

    float i = sigf(gi);
    float f = sigf(gf);
    float g = tanhf(gg);
    float o = sigf(go);
    float c = f * c_prev[(size_t)b * H_ + u] + i * g;
    float h = o * tanhf(c);
    c_out[(size_t)b * H_ + u] = c;
    h_out[(size_t)b * H_ + u] = h;
}

// ---------------------------------------------------------------------------
// Launch
// ---------------------------------------------------------------------------
extern "C" void kernel_launch(void* const* d_in, const int* in_sizes, int n_in,
                              void* d_out, int out_size) {
    const int*   input = (const int*)d_in[0];
    const float* h0    = (const float*)d_in[1];
    const float* c0    = (const float*)d_in[2];
    const float* emb   = (const float*)d_in[3];
    const float* W_ih  = (const float*)d_in[4];
    const float* W_hh  = (const float*)d_in[5];
    const float* b_ih  = (const float*)d_in[6];
    const float* b_hh  = (const float*)d_in[7];
    const float* dec_W = (const float*)d_in[8];
    const float* dec_b = (const float*)d_in[9];
    float* out = (float*)d_out;

    void* p;
    cudaGetSymbolAddress(&p, g_xb0);   float* xb0   = (float*)p;
    cudaGetSymbolAddress(&p, g_xb1);   float* xb1   = (float*)p;
    cudaGetSymbolAddress(&p, g_xproj); float* xproj = (float*)p;
    cudaGetSymbolAddress(&p, g_c);     float* gc    = (float*)p;

    // 1) embedding
    embed_kernel<<<TB, 256>>>(input, emb, xb0);

    const size_t D0 = (size_t)TB * V_;        // decoded size
    const size_t BH = (size_t)B_ * H_;

    for (int l = 0; l < L_; ++l) {
        const float* xin = l ? xb1 : xb0;
        float*       y   = l ? xb0 : xb1;

        // 2) input projection: xproj = xin @ W_ih[l]^T + b_ih[l] + b_hh[l]
        dim3 g1(G4H / BN, TB / BM);
        gemm_nt_bias<<<g1, 256>>>(xin, W_ih + (size_t)l * G4H * E_,
                                  b_ih + (size_t)l * G4H, b_hh + (size_t)l * G4H,
                                  xproj, TB, G4H, E_, G4H);

        // 3) recurrence
        for (int t = 0; t < T_; ++t) {
            const float* hp = t ? (y + (size_t)(t - 1) * BH) : (h0 + (size_t)l * BH);
            const float* cp = t ? (const float*)gc           : (c0 + (size_t)l * BH);
            lstm_step<<<H_ / UN, 256>>>(xproj + (size_t)t * B_ * G4H,
                                        W_hh + (size_t)l * G4H * H_,
                                        hp, cp, gc, y + (size_t)t * BH);
        }

        // hs / cs outputs
        cudaMemcpyAsync(out + D0 + (size_t)l * BH, y + (size_t)(T_ - 1) * BH,
                        BH * sizeof(float), cudaMemcpyDeviceToDevice, 0);
        cudaMemcpyAsync(out + D0 + (size_t)L_ * BH + (size_t)l * BH, gc,
                        BH * sizeof(float), cudaMemcpyDeviceToDevice, 0);
    }

    // 4) decoder: decoded = y_L1 @ dec_W^T + dec_b  (written straight to d_out)
    dim3 g2(V_ / BN, TB / BM);
    gemm_nt_bias<<<g2, 256>>>(xb0, dec_W, dec_b, nullptr, out, TB, V_, H_, V_);
}

// round 2
// speedup vs baseline: 1.1294x; 1.1294x over previous
#include <cuda_runtime.h>
#include <math.h>
#include <stdint.h>

// Problem constants
constexpr int T_ = 128, B_ = 32, L_ = 2, H_ = 1024, E_ = 1024, V_ = 32000;
constexpr int TB  = T_ * B_;     // 4096
constexpr int G4H = 4 * H_;      // 4096

constexpr int NBLK = 128;        // persistent blocks (<=148 SMs, 1/SM)
constexpr int NTHR = 256;
constexpr int KC   = 256;        // h chunk in floats
constexpr int KP   = KC / 2;     // 128 k-pairs per chunk
constexpr int S2   = 33;         // pair-row stride (in ull) for h smem

// Scratch (device globals: allocation-free rule)
__device__ float g_xb0[TB * E_];       // embed out / layer1 out
__device__ float g_xb1[TB * H_];       // layer0 out
__device__ float g_xproj[TB * G4H];    // per-layer input projection

// grid barrier state
__device__ unsigned g_cnt;
__device__ volatile unsigned g_gen;

// ---------------------------------------------------------------------------
// Embedding gather
// ---------------------------------------------------------------------------
__global__ void embed_kernel(const int* __restrict__ idx,
                             const float* __restrict__ emb,
                             float* __restrict__ out) {
    int tb = blockIdx.x;
    int v  = idx[tb];
    const float4* src = (const float4*)(emb + (size_t)v * E_);
    float4*       dst = (float4*)(out + (size_t)tb * E_);
    dst[threadIdx.x] = src[threadIdx.x];
}

// ---------------------------------------------------------------------------
// fp32 GEMM: C[M,N] = A[M,K] @ B[N,K]^T + bias1[n] + bias2[n]  (unchanged)
// ---------------------------------------------------------------------------
constexpr int BM = 128, BN = 128, BK = 16;

__global__ __launch_bounds__(256)
void gemm_nt_bias(const float* __restrict__ A, const float* __restrict__ B,
                  const float* __restrict__ bias1, const float* __restrict__ bias2,
                  float* __restrict__ C, int M, int N, int K, int ldc) {
    __shared__ float As[BK][BM + 4];
    __shared__ float Bs[BK][BN + 4];

    const int bx = blockIdx.x;
    const int by = blockIdx.y;
    const int tid = threadIdx.x;
    const int tcol = tid & 15;
    const int trow = tid >> 4;

    const float* Ag = A + (size_t)by * BM * K;
    const float* Bg = B + (size_t)bx * BN * K;

    float acc[8][8];
#pragma unroll
    for (int i = 0; i < 8; i++)
#pragma unroll
        for (int j = 0; j < 8; j++) acc[i][j] = 0.f;

    for (int kt = 0; kt < K; kt += BK) {
#pragma unroll
        for (int ld = 0; ld < 2; ld++) {
            int id  = tid + ld * 256;
            int row = id >> 2;
            int c4  = (id & 3) * 4;
            float4 av = *(const float4*)(Ag + (size_t)row * K + kt + c4);
            As[c4 + 0][row] = av.x; As[c4 + 1][row] = av.y;
            As[c4 + 2][row] = av.z; As[c4 + 3][row] = av.w;
            float4 bv = *(const float4*)(Bg + (size_t)row * K + kt + c4);
            Bs[c4 + 0][row] = bv.x; Bs[c4 + 1][row] = bv.y;
            Bs[c4 + 2][row] = bv.z; Bs[c4 + 3][row] = bv.w;
        }
        __syncthreads();

#pragma unroll
        for (int k = 0; k < BK; k++) {
            float4 a0 = *(const float4*)&As[k][trow * 8];
            float4 a1 = *(const float4*)&As[k][trow * 8 + 4];
            float4 b0 = *(const float4*)&Bs[k][tcol * 8];
            float4 b1 = *(const float4*)&Bs[k][tcol * 8 + 4];
            float ar[8] = {a0.x, a0.y, a0.z, a0.w, a1.x, a1.y, a1.z, a1.w};
            float br[8] = {b0.x, b0.y, b0.z, b0.w, b1.x, b1.y, b1.z, b1.w};
#pragma unroll
            for (int i = 0; i < 8; i++)
#pragma unroll
                for (int j = 0; j < 8; j++) acc[i][j] += ar[i] * br[j];
        }
        __syncthreads();
    }

    const int cn = bx * BN + tcol * 8;
    float bsum[8];
#pragma unroll
    for (int j = 0; j < 8; j++) {
        float bb = bias1 ? bias1[cn + j] : 0.f;
        if (bias2) bb += bias2[cn + j];
        bsum[j] = bb;
    }
#pragma unroll
    for (int i = 0; i < 8; i++) {
        size_t row = (size_t)(by * BM + trow * 8 + i);
        float4 o0, o1;
        o0.x = acc[i][0] + bsum[0]; o0.y = acc[i][1] + bsum[1];
        o0.z = acc[i][2] + bsum[2]; o0.w = acc[i][3] + bsum[3];
        o1.x = acc[i][4] + bsum[4]; o1.y = acc[i][5] + bsum[5];
        o1.z = acc[i][6] + bsum[6]; o1.w = acc[i][7] + bsum[7];
        *(float4*)(C + row * ldc + cn)     = o0;
        *(float4*)(C + row * ldc + cn + 4) = o1;
    }
}

// ---------------------------------------------------------------------------
// Persistent LSTM layer kernel
// ---------------------------------------------------------------------------
__device__ __forceinline__ float sigf(float x) { return 1.f / (1.f + expf(-x)); }

__device__ __forceinline__ unsigned long long ffma2(unsigned long long a,
                                                    unsigned long long b,
                                                    unsigned long long c) {
    unsigned long long d;
    asm("fma.rn.f32x2 %0, %1, %2, %3;" : "=l"(d) : "l"(a), "l"(b), "l"(c));
    return d;
}

// smem layout (dynamic):
constexpr int SW_BYTES  = 32 * 1024 * 4;         // W tile  [32 rows][1024]
constexpr int SH2_BYTES = KP * S2 * 8;           // h chunk [128 pairs][33] ull
constexpr int SG_BYTES  = 32 * 33 * 4;           // gates   [32 rows][33]
constexpr int SMEM_LSTM = SW_BYTES + SH2_BYTES + SG_BYTES;  // 169,088 B

__global__ __launch_bounds__(NTHR, 1)
void lstm_persist(const float* __restrict__ xproj,   // [T*B][4H]
                  const float* __restrict__ Whh,     // [4H][H]
                  const float* __restrict__ h0l,     // [B][H]
                  const float* __restrict__ c0l,     // [B][H]
                  float* __restrict__ y,             // [T][B][H]
                  float* __restrict__ hs_out,        // [B][H]
                  float* __restrict__ cs_out) {      // [B][H]
    extern __shared__ char smem_raw[];
    float*              sw  = (float*)smem_raw;                         // [32][1024]
    unsigned long long* sh2 = (unsigned long long*)(smem_raw + SW_BYTES);
    float*              sg  = (float*)(smem_raw + SW_BYTES + SH2_BYTES);

    const int tid  = threadIdx.x;
    const int blk  = blockIdx.x;
    const int n0   = blk * 8;           // 8 hidden units owned by this block
    const int wrp  = tid >> 5;          // warp handles rows 4*wrp..4*wrp+3
    const int lane = tid & 31;          // batch = lane
    const int b2   = tid >> 3;          // phase-2 batch
    const int u2   = tid & 7;           // phase-2 unit-within-block

    // Load W_hh rows for this block. row r -> global row (r>>3)*H + n0 + (r&7)
    for (int i = tid; i < 32 * 256; i += NTHR) {
        int r   = i >> 8;
        int k4  = (i & 255) * 4;
        int gr  = ((r >> 3) * H_) + n0 + (r & 7);
        *(float4*)&sw[r * 1024 + k4] = *(const float4*)&Whh[(size_t)gr * H_ + k4];
    }

    __shared__ unsigned s_base;
    if (tid == 0) s_base = g_gen;   // safe: no block can release a barrier
                                    // before this block arrives (after this read)

    float c_reg = c0l[b2 * H_ + n0 + u2];

    __syncthreads();
    const unsigned base = s_base;

    for (int t = 0; t < T_; ++t) {
        const float* hp = t ? (y + (size_t)(t - 1) * B_ * H_) : h0l;

        // prefetch chunk 0 of h into registers
        float4 pf[8];
#pragma unroll
        for (int i = 0; i < 8; i++) {
            int id = tid + i * NTHR;           // 0..2047
            int b  = id >> 6, k4 = id & 63;
            pf[i] = __ldcg((const float4*)(hp + (size_t)b * H_) + k4);
        }

        unsigned long long acc[4] = {0ull, 0ull, 0ull, 0ull};  // f32x2 zeros

        for (int c = 0; c < 4; ++c) {
            // store prefetched chunk to smem as k-pair ulls: sh2[pair][batch]
#pragma unroll
            for (int i = 0; i < 8; i++) {
                int id = tid + i * NTHR;
                int b  = id >> 6, k4 = id & 63;
                int p  = k4 * 2;
                sh2[(size_t)p * S2 + b]       = *(unsigned long long*)&pf[i].x;
                sh2[(size_t)(p + 1) * S2 + b] = *(unsigned long long*)&pf[i].z;
            }
            __syncthreads();

            // prefetch next chunk (global latency hidden behind compute)
            if (c < 3) {
                int k0n = (c + 1) * KC;
#pragma unroll
                for (int i = 0; i < 8; i++) {
                    int id = tid + i * NTHR;
                    int b  = id >> 6, k4 = id & 63;
                    pf[i] = __ldcg((const float4*)(hp + (size_t)b * H_ + k0n) + k4);
                }
            }

            // compute: 4 rows x 32 batches over this 256-k chunk
            const float* wbase = sw + (wrp * 4) * 1024 + c * KC;
            const unsigned long long* hb = sh2 + lane;
#pragma unroll 4
            for (int p = 0; p < KP; p += 2) {      // 4 floats (2 pairs) per iter
                unsigned long long h01 = hb[(size_t)p * S2];
                unsigned long long h23 = hb[(size_t)(p + 1) * S2];
#pragma unroll
                for (int j = 0; j < 4; j++) {
                    double2 wv = *(const double2*)(wbase + j * 1024 + p * 2);
                    acc[j] = ffma2(__double_as_longlong(wv.x), h01, acc[j]);
                    acc[j] = ffma2(__double_as_longlong(wv.y), h23, acc[j]);
                }
            }
            __syncthreads();   // sh2 reusable next chunk
        }

        // write gate pre-activations: sg[row][batch]
#pragma unroll
        for (int j = 0; j < 4; j++) {
            union { unsigned long long u; float2 f; } cv;
            cv.u = acc[j];
            sg[(wrp * 4 + j) * 33 + lane] = cv.f.x + cv.f.y;
        }
        __syncthreads();

        // phase 2: one thread per (batch b2, unit u2)
        const float* xp = xproj + ((size_t)t * B_ + b2) * G4H + n0 + u2;
        float gi = sg[(0 * 8 + u2) * 33 + b2] + xp[0 * H_];
        float gf = sg[(1 * 8 + u2) * 33 + b2] + xp[1 * H_];
        float gg = sg[(2 * 8 + u2) * 33 + b2] + xp[2 * H_];
        float go = sg[(3 * 8 + u2) * 33 + b2] + xp[3 * H_];

        float i = sigf(gi);
        float f = sigf(gf);
        float g = tanhf(gg);
        float o = sigf(go);
        c_reg   = f * c_reg + i * g;
        float h = o * tanhf(c_reg);

        y[(size_t)t * B_ * H_ + b2 * H_ + n0 + u2] = h;
        if (t == T_ - 1) {
            hs_out[b2 * H_ + n0 + u2] = h;
            cs_out[b2 * H_ + n0 + u2] = c_reg;
        }

        // grid barrier: release h[t] to all blocks
        __syncthreads();
        if (tid == 0) {
            unsigned target = base + (unsigned)(t + 1);
            __threadfence();
            unsigned arr = atomicAdd(&g_cnt, 1u);
            if (arr == NBLK - 1) {
                g_cnt = 0;
                __threadfence();
                g_gen = target;
            } else {
                while ((int)(g_gen - target) < 0) { __nanosleep(32); }
            }
        }
        __syncthreads();
    }
}

// ---------------------------------------------------------------------------
// Launch
// ---------------------------------------------------------------------------
extern "C" void kernel_launch(void* const* d_in, const int* in_sizes, int n_in,
                              void* d_out, int out_size) {
    const int*   input = (const int*)d_in[0];
    const float* h0    = (const float*)d_in[1];
    const float* c0    = (const float*)d_in[2];
    const float* emb   = (const float*)d_in[3];
    const float* W_ih  = (const float*)d_in[4];
    const float* W_hh  = (const float*)d_in[5];
    const float* b_ih  = (const float*)d_in[6];
    const float* b_hh  = (const float*)d_in[7];
    const float* dec_W = (const float*)d_in[8];
    const float* dec_b = (const float*)d_in[9];
    float* out = (float*)d_out;

    void* p;
    cudaGetSymbolAddress(&p, g_xb0);   float* xb0   = (float*)p;
    cudaGetSymbolAddress(&p, g_xb1);   float* xb1   = (float*)p;
    cudaGetSymbolAddress(&p, g_xproj); float* xproj = (float*)p;

    cudaFuncSetAttribute(lstm_persist,
                         cudaFuncAttributeMaxDynamicSharedMemorySize, SMEM_LSTM);

    // 1) embedding
    embed_kernel<<<TB, 256>>>(input, emb, xb0);

    const size_t D0 = (size_t)TB * V_;
    const size_t BH = (size_t)B_ * H_;

    for (int l = 0; l < L_; ++l) {
        const float* xin = l ? xb1 : xb0;
        float*       y   = l ? xb0 : xb1;

        // 2) input projection: xproj = xin @ W_ih[l]^T + b_ih[l] + b_hh[l]
        dim3 g1(G4H / BN, TB / BM);
        gemm_nt_bias<<<g1, 256>>>(xin, W_ih + (size_t)l * G4H * E_,
                                  b_ih + (size_t)l * G4H, b_hh + (size_t)l * G4H,
                                  xproj, TB, G4H, E_, G4H);

        // 3) full recurrence in ONE persistent launch
        lstm_persist<<<NBLK, NTHR, SMEM_LSTM>>>(
            xproj, W_hh + (size_t)l * G4H * H_,
            h0 + (size_t)l * BH, c0 + (size_t)l * BH,
            y,
            out + D0 + (size_t)l * BH,
            out + D0 + (size_t)L_ * BH + (size_t)l * BH);
    }

    // 4) decoder
    dim3 g2(V_ / BN, TB / BM);
    gemm_nt_bias<<<g2, 256>>>(xb0, dec_W, dec_b, nullptr, out, TB, V_, H_, V_);
}

// round 3
// speedup vs baseline: 1.1348x; 1.0048x over previous
#include <cuda_runtime.h>
#include <math.h>
#include <stdint.h>

// Problem constants
constexpr int T_ = 128, B_ = 32, L_ = 2, H_ = 1024, E_ = 1024, V_ = 32000;
constexpr int TB  = T_ * B_;     // 4096
constexpr int G4H = 4 * H_;      // 4096

constexpr int NBLK = 128;        // persistent blocks
constexpr int NTHR = 256;
constexpr int KC   = 256;        // h chunk in floats
constexpr int KP   = KC / 2;     // 128 k-pairs per chunk
constexpr int S2   = 33;         // pair-row stride (ull) for h smem

// Scratch (device globals: allocation-free rule)
__device__ float g_xb0[TB * E_];       // embed out / layer1 out
__device__ float g_xb1[TB * H_];       // layer0 out
__device__ float g_xproj[TB * G4H];    // per-layer input projection
__device__ float g_decw[(size_t)V_ * H_];  // tf32-rounded decoder weight

// grid barrier state
__device__ unsigned g_cnt;
__device__ volatile unsigned g_gen;

// ---------------------------------------------------------------------------
// Embedding gather
// ---------------------------------------------------------------------------
__global__ void embed_kernel(const int* __restrict__ idx,
                             const float* __restrict__ emb,
                             float* __restrict__ out) {
    int tb = blockIdx.x;
    int v  = idx[tb];
    const float4* src = (const float4*)(emb + (size_t)v * E_);
    float4*       dst = (float4*)(out + (size_t)tb * E_);
    dst[threadIdx.x] = src[threadIdx.x];
}

// ---------------------------------------------------------------------------
// tf32 rounding (RNA) kernels: out[i] = round_tf32(in[i])
// ---------------------------------------------------------------------------
__device__ __forceinline__ float to_tf32(float x) {
    unsigned u;
    asm("cvt.rna.tf32.f32 %0, %1;" : "=r"(u) : "f"(x));
    return __uint_as_float(u);
}

__global__ void round_tf32_kernel(const float* __restrict__ in,
                                  float* __restrict__ out, int nf4) {
    int i = blockIdx.x * blockDim.x + threadIdx.x;
    if (i >= nf4) return;
    float4 v = ((const float4*)in)[i];
    v.x = to_tf32(v.x); v.y = to_tf32(v.y);
    v.z = to_tf32(v.z); v.w = to_tf32(v.w);
    ((float4*)out)[i] = v;
}

// ---------------------------------------------------------------------------
// fp32 GEMM (xproj only): C[M,N] = A[M,K] @ B[N,K]^T + bias1 + bias2
// ---------------------------------------------------------------------------
constexpr int BM = 128, BN = 128, BK = 16;

__global__ __launch_bounds__(256)
void gemm_nt_bias(const float* __restrict__ A, const float* __restrict__ B,
                  const float* __restrict__ bias1, const float* __restrict__ bias2,
                  float* __restrict__ C, int M, int N, int K, int ldc) {
    __shared__ float As[BK][BM + 4];
    __shared__ float Bs[BK][BN + 4];

    const int bx = blockIdx.x;
    const int by = blockIdx.y;
    const int tid = threadIdx.x;
    const int tcol = tid & 15;
    const int trow = tid >> 4;

    const float* Ag = A + (size_t)by * BM * K;
    const float* Bg = B + (size_t)bx * BN * K;

    float acc[8][8];
#pragma unroll
    for (int i = 0; i < 8; i++)
#pragma unroll
        for (int j = 0; j < 8; j++) acc[i][j] = 0.f;

    for (int kt = 0; kt < K; kt += BK) {
#pragma unroll
        for (int ld = 0; ld < 2; ld++) {
            int id  = tid + ld * 256;
            int row = id >> 2;
            int c4  = (id & 3) * 4;
            float4 av = *(const float4*)(Ag + (size_t)row * K + kt + c4);
            As[c4 + 0][row] = av.x; As[c4 + 1][row] = av.y;
            As[c4 + 2][row] = av.z; As[c4 + 3][row] = av.w;
            float4 bv = *(const float4*)(Bg + (size_t)row * K + kt + c4);
            Bs[c4 + 0][row] = bv.x; Bs[c4 + 1][row] = bv.y;
            Bs[c4 + 2][row] = bv.z; Bs[c4 + 3][row] = bv.w;
        }
        __syncthreads();

#pragma unroll
        for (int k = 0; k < BK; k++) {
            float4 a0 = *(const float4*)&As[k][trow * 8];
            float4 a1 = *(const float4*)&As[k][trow * 8 + 4];
            float4 b0 = *(const float4*)&Bs[k][tcol * 8];
            float4 b1 = *(const float4*)&Bs[k][tcol * 8 + 4];
            float ar[8] = {a0.x, a0.y, a0.z, a0.w, a1.x, a1.y, a1.z, a1.w};
            float br[8] = {b0.x, b0.y, b0.z, b0.w, b1.x, b1.y, b1.z, b1.w};
#pragma unroll
            for (int i = 0; i < 8; i++)
#pragma unroll
                for (int j = 0; j < 8; j++) acc[i][j] += ar[i] * br[j];
        }
        __syncthreads();
    }

    const int cn = bx * BN + tcol * 8;
    float bsum[8];
#pragma unroll
    for (int j = 0; j < 8; j++) {
        float bb = bias1 ? bias1[cn + j] : 0.f;
        if (bias2) bb += bias2[cn + j];
        bsum[j] = bb;
    }
#pragma unroll
    for (int i = 0; i < 8; i++) {
        size_t row = (size_t)(by * BM + trow * 8 + i);
        float4 o0, o1;
        o0.x = acc[i][0] + bsum[0]; o0.y = acc[i][1] + bsum[1];
        o0.z = acc[i][2] + bsum[2]; o0.w = acc[i][3] + bsum[3];
        o1.x = acc[i][4] + bsum[4]; o1.y = acc[i][5] + bsum[5];
        o1.z = acc[i][6] + bsum[6]; o1.w = acc[i][7] + bsum[7];
        *(float4*)(C + row * ldc + cn)     = o0;
        *(float4*)(C + row * ldc + cn + 4) = o1;
    }
}

// ---------------------------------------------------------------------------
// tf32 tensor-core GEMM (decoder): C[M,N] = A[M,K] @ B[N,K]^T + bias
// M=4096, N=32000, K=1024. 128x128x32 tiles, mma.sync m16n8k8.
// Inputs must already be tf32-rounded fp32.
// ---------------------------------------------------------------------------
constexpr int DM = 4096, DN = 32000, DK = 1024;
constexpr int DMT = DM / 128;    // 32
constexpr int DNT = DN / 128;    // 250
constexpr int DCH = 50;          // N-tiles per L2 chunk (250 = 5 * 50)

__device__ __forceinline__ void cp_async16(unsigned saddr, const void* gptr) {
    asm volatile("cp.async.cg.shared.global [%0], [%1], 16;\n"
                 :: "r"(saddr), "l"(gptr));
}
__device__ __forceinline__ void cp_commit() {
    asm volatile("cp.async.commit_group;\n");
}
template <int N>
__device__ __forceinline__ void cp_wait() {
    asm volatile("cp.async.wait_group %0;\n" :: "n"(N));
}

__device__ __forceinline__ void mma_tf32(float* d, const float* a, const float* b) {
    asm volatile(
        "mma.sync.aligned.m16n8k8.row.col.f32.tf32.tf32.f32 "
        "{%0,%1,%2,%3},{%4,%5,%6,%7},{%8,%9},{%0,%1,%2,%3};\n"
        : "+f"(d[0]), "+f"(d[1]), "+f"(d[2]), "+f"(d[3])
        : "r"(__float_as_uint(a[0])), "r"(__float_as_uint(a[1])),
          "r"(__float_as_uint(a[2])), "r"(__float_as_uint(a[3])),
          "r"(__float_as_uint(b[0])), "r"(__float_as_uint(b[1])));
}

__global__ __launch_bounds__(256, 2)
void gemm_tf32_dec(const float* __restrict__ A, const float* __restrict__ Bw,
                   const float* __restrict__ bias, float* __restrict__ C) {
    __shared__ float sA[2][128 * 32];
    __shared__ float sB[2][128 * 32];

    // block swizzle for L2 reuse: chunks of DCH N-tiles across all M-tiles
    const int lid   = blockIdx.x;
    const int chunk = lid / (DMT * DCH);
    const int idw   = lid % (DMT * DCH);
    const int bn    = chunk * DCH + idw % DCH;
    const int bm    = idw / DCH;

    const int tid  = threadIdx.x;
    const int wid  = tid >> 5;
    const int lane = tid & 31;
    const int gid  = lane >> 2;   // groupID 0..7
    const int tig  = lane & 3;    // thread-in-group 0..3
    const int wm   = wid >> 2;    // 0..1
    const int wn   = wid & 3;     // 0..3

    // per-thread global-load assignment (4 float4 per matrix per k-tile)
    int lrow[4], lcb[4];
    unsigned sAu = (unsigned)__cvta_generic_to_shared(&sA[0][0]);
    unsigned sBu = (unsigned)__cvta_generic_to_shared(&sB[0][0]);
#pragma unroll
    for (int i = 0; i < 4; i++) {
        int f = tid + i * 256;           // 0..1023
        lrow[i] = f >> 3;                // 0..127
        lcb[i]  = f & 7;                 // float4-block 0..7
    }

    const float* Ag = A  + (size_t)(bm * 128) * DK;
    const float* Bg = Bw + (size_t)(bn * 128) * DK;

    auto issue = [&](int kt, int buf) {
#pragma unroll
        for (int i = 0; i < 4; i++) {
            int row = lrow[i], cb = lcb[i];
            unsigned soff = (unsigned)((row * 32 + ((cb ^ (row & 7)) << 2)) * 4
                                       + buf * 128 * 32 * 4);
            cp_async16(sAu + soff, Ag + (size_t)row * DK + kt * 32 + cb * 4);
            cp_async16(sBu + soff, Bg + (size_t)row * DK + kt * 32 + cb * 4);
        }
        cp_commit();
    };

    float acc[4][4][4];
#pragma unroll
    for (int i = 0; i < 4; i++)
#pragma unroll
        for (int j = 0; j < 4; j++)
#pragma unroll
            for (int k = 0; k < 4; k++) acc[i][j][k] = 0.f;

    issue(0, 0);

    const int NKT = DK / 32;   // 32
    for (int kt = 0; kt < NKT; ++kt) {
        int cur = kt & 1;
        if (kt + 1 < NKT) { issue(kt + 1, cur ^ 1); cp_wait<1>(); }
        else              { cp_wait<0>(); }
        __syncthreads();

        const float* cA = sA[cur];
        const float* cB = sB[cur];
#pragma unroll
        for (int s = 0; s < 4; s++) {
            int kb0 = (s * 2) ^ gid;
            int kb1 = (s * 2 + 1) ^ gid;
            float a[4][4], b[4][2];
#pragma unroll
            for (int tm = 0; tm < 4; tm++) {
                int r0 = (wm * 64 + tm * 16 + gid) * 32;
                a[tm][0] = cA[r0 + (kb0 << 2) + tig];
                a[tm][1] = cA[r0 + 256 + (kb0 << 2) + tig];
                a[tm][2] = cA[r0 + (kb1 << 2) + tig];
                a[tm][3] = cA[r0 + 256 + (kb1 << 2) + tig];
            }
#pragma unroll
            for (int tn = 0; tn < 4; tn++) {
                int rb = (wn * 32 + tn * 8 + gid) * 32;
                b[tn][0] = cB[rb + (kb0 << 2) + tig];
                b[tn][1] = cB[rb + (kb1 << 2) + tig];
            }
#pragma unroll
            for (int tm = 0; tm < 4; tm++)
#pragma unroll
                for (int tn = 0; tn < 4; tn++)
                    mma_tf32(acc[tm][tn], a[tm], b[tn]);
        }
        __syncthreads();
    }

    // epilogue: bias + store
#pragma unroll
    for (int tm = 0; tm < 4; tm++) {
        int row0 = bm * 128 + wm * 64 + tm * 16 + gid;
#pragma unroll
        for (int tn = 0; tn < 4; tn++) {
            int col = bn * 128 + wn * 32 + tn * 8 + 2 * tig;
            float b0 = bias[col], b1 = bias[col + 1];
            float2 v0 = make_float2(acc[tm][tn][0] + b0, acc[tm][tn][1] + b1);
            float2 v1 = make_float2(acc[tm][tn][2] + b0, acc[tm][tn][3] + b1);
            *(float2*)(C + (size_t)row0 * DN + col)       = v0;
            *(float2*)(C + (size_t)(row0 + 8) * DN + col) = v1;
        }
    }
}

// ---------------------------------------------------------------------------
// Persistent LSTM layer kernel (unchanged from round 2)
// ---------------------------------------------------------------------------
__device__ __forceinline__ float sigf(float x) { return 1.f / (1.f + expf(-x)); }

__device__ __forceinline__ unsigned long long ffma2(unsigned long long a,
                                                    unsigned long long b,
                                                    unsigned long long c) {
    unsigned long long d;
    asm("fma.rn.f32x2 %0, %1, %2, %3;" : "=l"(d) : "l"(a), "l"(b), "l"(c));
    return d;
}

constexpr int SW_BYTES  = 32 * 1024 * 4;
constexpr int SH2_BYTES = KP * S2 * 8;
constexpr int SG_BYTES  = 32 * 33 * 4;
constexpr int SMEM_LSTM = SW_BYTES + SH2_BYTES + SG_BYTES;

__global__ __launch_bounds__(NTHR, 1)
void lstm_persist(const float* __restrict__ xproj,
                  const float* __restrict__ Whh,
                  const float* __restrict__ h0l,
                  const float* __restrict__ c0l,
                  float* __restrict__ y,
                  float* __restrict__ hs_out,
                  float* __restrict__ cs_out) {
    extern __shared__ char smem_raw[];
    float*              sw  = (float*)smem_raw;
    unsigned long long* sh2 = (unsigned long long*)(smem_raw + SW_BYTES);
    float*              sg  = (float*)(smem_raw + SW_BYTES + SH2_BYTES);

    const int tid  = threadIdx.x;
    const int blk  = blockIdx.x;
    const int n0   = blk * 8;
    const int wrp  = tid >> 5;
    const int lane = tid & 31;
    const int b2   = tid >> 3;
    const int u2   = tid & 7;

    for (int i = tid; i < 32 * 256; i += NTHR) {
        int r   = i >> 8;
        int k4  = (i & 255) * 4;
        int gr  = ((r >> 3) * H_) + n0 + (r & 7);
        *(float4*)&sw[r * 1024 + k4] = *(const float4*)&Whh[(size_t)gr * H_ + k4];
    }

    __shared__ unsigned s_base;
    if (tid == 0) s_base = g_gen;

    float c_reg = c0l[b2 * H_ + n0 + u2];

    __syncthreads();
    const unsigned base = s_base;

    for (int t = 0; t < T_; ++t) {
        const float* hp = t ? (y + (size_t)(t - 1) * B_ * H_) : h0l;

        float4 pf[8];
#pragma unroll
        for (int i = 0; i < 8; i++) {
            int id = tid + i * NTHR;
            int b  = id >> 6, k4 = id & 63;
            pf[i] = __ldcg((const float4*)(hp + (size_t)b * H_) + k4);
        }

        unsigned long long acc[4] = {0ull, 0ull, 0ull, 0ull};

        for (int c = 0; c < 4; ++c) {
#pragma unroll
            for (int i = 0; i < 8; i++) {
                int id = tid + i * NTHR;
                int b  = id >> 6, k4 = id & 63;
                int p  = k4 * 2;
                sh2[(size_t)p * S2 + b]       = *(unsigned long long*)&pf[i].x;
                sh2[(size_t)(p + 1) * S2 + b] = *(unsigned long long*)&pf[i].z;
            }
            __syncthreads();

            if (c < 3) {
                int k0n = (c + 1) * KC;
#pragma unroll
                for (int i = 0; i < 8; i++) {
                    int id = tid + i * NTHR;
                    int b  = id >> 6, k4 = id & 63;
                    pf[i] = __ldcg((const float4*)(hp + (size_t)b * H_ + k0n) + k4);
                }
            }

            const float* wbase = sw + (wrp * 4) * 1024 + c * KC;
            const unsigned long long* hb = sh2 + lane;
#pragma unroll 4
            for (int p = 0; p < KP; p += 2) {
                unsigned long long h01 = hb[(size_t)p * S2];
                unsigned long long h23 = hb[(size_t)(p + 1) * S2];
#pragma unroll
                for (int j = 0; j < 4; j++) {
                    double2 wv = *(const double2*)(wbase + j * 1024 + p * 2);
                    acc[j] = ffma2(__double_as_longlong(wv.x), h01, acc[j]);
                    acc[j] = ffma2(__double_as_longlong(wv.y), h23, acc[j]);
                }
            }
            __syncthreads();
        }

#pragma unroll
        for (int j = 0; j < 4; j++) {
            union { unsigned long long u; float2 f; } cv;
            cv.u = acc[j];
            sg[(wrp * 4 + j) * 33 + lane] = cv.f.x + cv.f.y;
        }
        __syncthreads();

        const float* xp = xproj + ((size_t)t * B_ + b2) * G4H + n0 + u2;
        float gi = sg[(0 * 8 + u2) * 33 + b2] + xp[0 * H_];
        float gf = sg[(1 * 8 + u2) * 33 + b2] + xp[1 * H_];
        float gg = sg[(2 * 8 + u2) * 33 + b2] + xp[2 * H_];
        float go = sg[(3 * 8 + u2) * 33 + b2] + xp[3 * H_];

        float i = sigf(gi);
        float f = sigf(gf);
        float g = tanhf(gg);
        float o = sigf(go);
        c_reg   = f * c_reg + i * g;
        float h = o * tanhf(c_reg);

        y[(size_t)t * B_ * H_ + b2 * H_ + n0 + u2] = h;
        if (t == T_ - 1) {
            hs_out[b2 * H_ + n0 + u2] = h;
            cs_out[b2 * H_ + n0 + u2] = c_reg;
        }

        __syncthreads();
        if (tid == 0) {
            unsigned target = base + (unsigned)(t + 1);
            __threadfence();
            unsigned arr = atomicAdd(&g_cnt, 1u);
            if (arr == NBLK - 1) {
                g_cnt = 0;
                __threadfence();
                g_gen = target;
            } else {
                while ((int)(g_gen - target) < 0) { __nanosleep(32); }
            }
        }
        __syncthreads();
    }
}

// ---------------------------------------------------------------------------
// Launch
// ---------------------------------------------------------------------------
extern "C" void kernel_launch(void* const* d_in, const int* in_sizes, int n_in,
                              void* d_out, int out_size) {
    const int*   input = (const int*)d_in[0];
    const float* h0    = (const float*)d_in[1];
    const float* c0    = (const float*)d_in[2];
    const float* emb   = (const float*)d_in[3];
    const float* W_ih  = (const float*)d_in[4];
    const float* W_hh  = (const float*)d_in[5];
    const float* b_ih  = (const float*)d_in[6];
    const float* b_hh  = (const float*)d_in[7];
    const float* dec_W = (const float*)d_in[8];
    const float* dec_b = (const float*)d_in[9];
    float* out = (float*)d_out;

    void* p;
    cudaGetSymbolAddress(&p, g_xb0);   float* xb0   = (float*)p;
    cudaGetSymbolAddress(&p, g_xb1);   float* xb1   = (float*)p;
    cudaGetSymbolAddress(&p, g_xproj); float* xproj = (float*)p;
    cudaGetSymbolAddress(&p, g_decw);  float* decw  = (float*)p;

    cudaFuncSetAttribute(lstm_persist,
                         cudaFuncAttributeMaxDynamicSharedMemorySize, SMEM_LSTM);

    // 1) embedding
    embed_kernel<<<TB, 256>>>(input, emb, xb0);

    // 1b) pre-round decoder weight to tf32 (independent of LSTM work)
    {
        int nf4 = (int)(((size_t)V_ * H_) / 4);
        round_tf32_kernel<<<(nf4 + 255) / 256, 256>>>(dec_W, decw, nf4);
    }

    const size_t D0 = (size_t)TB * V_;
    const size_t BH = (size_t)B_ * H_;

    for (int l = 0; l < L_; ++l) {
        const float* xin = l ? xb1 : xb0;
        float*       y   = l ? xb0 : xb1;

        dim3 g1(G4H / BN, TB / BM);
        gemm_nt_bias<<<g1, 256>>>(xin, W_ih + (size_t)l * G4H * E_,
                                  b_ih + (size_t)l * G4H, b_hh + (size_t)l * G4H,
                                  xproj, TB, G4H, E_, G4H);

        lstm_persist<<<NBLK, NTHR, SMEM_LSTM>>>(
            xproj, W_hh + (size_t)l * G4H * H_,
            h0 + (size_t)l * BH, c0 + (size_t)l * BH,
            y,
            out + D0 + (size_t)l * BH,
            out + D0 + (size_t)L_ * BH + (size_t)l * BH);
    }

    // 3b) round final activations to tf32 in place (only decoder reads them now)
    {
        int nf4 = (TB * H_) / 4;
        round_tf32_kernel<<<(nf4 + 255) / 256, 256>>>(xb0, xb0, nf4);
    }

    // 4) decoder on tensor cores
    gemm_tf32_dec<<<DMT * DNT, 256>>>(xb0, decw, dec_b, out);
}

// round 5
// speedup vs baseline: 2.0916x; 1.8432x over previous
#include <cuda_runtime.h>
#include <cuda_fp16.h>
#include <math.h>
#include <stdint.h>

// Problem constants
constexpr int T_ = 128, B_ = 32, L_ = 2, H_ = 1024, E_ = 1024, V_ = 32000;
constexpr int TB  = T_ * B_;     // 4096
constexpr int G4H = 4 * H_;      // 4096

constexpr int NBLK = 128;        // persistent blocks (LSTM)
constexpr int NTHR = 256;
constexpr int KC   = 256;
constexpr int KP   = KC / 2;
constexpr int S2   = 33;

// fp16 GEMM constants
constexpr int K2 = 2048;         // 2-term augmented K (decoder)
constexpr int K3 = 3072;         // 3-term augmented K (xproj)
constexpr int GEMM_SMEM = 3 * 32768;   // 3 stages x (A 16KB + B 16KB)

// Scratch (device globals)
__device__ float g_xb0[TB * E_];
__device__ float g_xb1[TB * H_];
__device__ float g_xproj[TB * G4H];
__device__ alignas(256) __half g_auga[(size_t)TB * K3];          // 25MB
__device__ alignas(256) __half g_augwih[(size_t)L_ * G4H * K3];  // 50MB
__device__ alignas(256) __half g_augdec[(size_t)V_ * K2];        // 131MB

// grid barrier state (LSTM)
__device__ unsigned g_cnt;
__device__ volatile unsigned g_gen;

// ---------------------------------------------------------------------------
// Embedding gather
// ---------------------------------------------------------------------------
__global__ void embed_kernel(const int* __restrict__ idx,
                             const float* __restrict__ emb,
                             float* __restrict__ out) {
    int tb = blockIdx.x;
    int v  = idx[tb];
    const float4* src = (const float4*)(emb + (size_t)v * E_);
    float4*       dst = (float4*)(out + (size_t)tb * E_);
    dst[threadIdx.x] = src[threadIdx.x];
}

// ---------------------------------------------------------------------------
// fp16 hi/lo augmentation: fp32 [rows][1024] -> fp16 [rows][nseg*1024]
// mode 0 (A 2-term): [hi | lo]        mode 1 (B 2-term): [hi | hi]
// mode 2 (A 3-term): [hi | hi | lo]   mode 3 (B 3-term): [hi | lo | hi]
// ---------------------------------------------------------------------------
__global__ void augh_kernel(const float* __restrict__ in,
                            __half* __restrict__ out, int mode) {
    const int nseg   = (mode >= 2) ? 3 : 2;
    const int stride = nseg * 1024;
    int r  = blockIdx.x;
    int k4 = threadIdx.x << 2;
    float4 x = *(const float4*)(in + (size_t)r * 1024 + k4);

    float xs[4] = {x.x, x.y, x.z, x.w};
    __half h[4], l[4];
#pragma unroll
    for (int j = 0; j < 4; j++) {
        h[j] = __float2half_rn(xs[j]);
        l[j] = __float2half_rn(xs[j] - __half2float(h[j]));
    }
    unsigned long long hv, lv;
    {
        unsigned short* hp = (unsigned short*)&hv;
        unsigned short* lp = (unsigned short*)&lv;
#pragma unroll
        for (int j = 0; j < 4; j++) {
            hp[j] = *(unsigned short*)&h[j];
            lp[j] = *(unsigned short*)&l[j];
        }
    }
    __half* base = out + (size_t)r * stride + k4;
    *(unsigned long long*)(base) = hv;
    unsigned long long s1 = (mode == 0 || mode == 3) ? lv : hv;
    *(unsigned long long*)(base + 1024) = s1;
    if (nseg == 3) {
        unsigned long long s2 = (mode == 2) ? lv : hv;
        *(unsigned long long*)(base + 2048) = s2;
    }
}

// ---------------------------------------------------------------------------
// low-level helpers
// ---------------------------------------------------------------------------
__device__ __forceinline__ uint32_t smem_u32(const void* p) {
    uint32_t a;
    asm("{ .reg .u64 t; cvta.to.shared.u64 t, %1; cvt.u32.u64 %0, t; }"
        : "=r"(a) : "l"(p));
    return a;
}
__device__ __forceinline__ void cp_async16(uint32_t saddr, const void* gptr) {
    asm volatile("cp.async.cg.shared.global [%0], [%1], 16;\n"
                 :: "r"(saddr), "l"(gptr));
}
__device__ __forceinline__ void cp_commit() {
    asm volatile("cp.async.commit_group;\n");
}
template <int N>
__device__ __forceinline__ void cp_wait() {
    asm volatile("cp.async.wait_group %0;\n" :: "n"(N));
}
__device__ __forceinline__ void ldsm4(uint32_t& r0, uint32_t& r1,
                                      uint32_t& r2, uint32_t& r3, uint32_t a) {
    asm volatile("ldmatrix.sync.aligned.m8n8.x4.shared.b16 {%0,%1,%2,%3},[%4];"
                 : "=r"(r0), "=r"(r1), "=r"(r2), "=r"(r3) : "r"(a));
}
__device__ __forceinline__ void ldsm2(uint32_t& r0, uint32_t& r1, uint32_t a) {
    asm volatile("ldmatrix.sync.aligned.m8n8.x2.shared.b16 {%0,%1},[%2];"
                 : "=r"(r0), "=r"(r1) : "r"(a));
}
__device__ __forceinline__ void mma16816(float* c, const uint32_t* a,
                                         const uint32_t* b) {
    asm volatile(
        "mma.sync.aligned.m16n8k16.row.col.f32.f16.f16.f32 "
        "{%0,%1,%2,%3},{%4,%5,%6,%7},{%8,%9},{%0,%1,%2,%3};"
        : "+f"(c[0]), "+f"(c[1]), "+f"(c[2]), "+f"(c[3])
        : "r"(a[0]), "r"(a[1]), "r"(a[2]), "r"(a[3]), "r"(b[0]), "r"(b[1]));
}

// ---------------------------------------------------------------------------
// fp16 mma.sync GEMM: C[4096, N] = A[4096, K] @ B[N, K]^T + bias1 + bias2
// 128x128 tiles, BK = 64 halves, 3-stage cp.async pipeline.
// grid.x = (N/128) * 32;  bm = bid & 31, bn = bid >> 5.
// ---------------------------------------------------------------------------
__global__ __launch_bounds__(256, 2)
void gemm_fp16_mma(const __half* __restrict__ A, const __half* __restrict__ B,
                   const float* __restrict__ bias1, const float* __restrict__ bias2,
                   float* __restrict__ C, int K, int ldc) {
    extern __shared__ char sm[];
    const int tid  = threadIdx.x;
    const int lane = tid & 31;
    const int wid  = tid >> 5;
    const int bm   = blockIdx.x & 31;
    const int bn   = blockIdx.x >> 5;
    const int wm   = wid >> 2;    // 0..1  -> 64 rows
    const int wn   = wid & 3;     // 0..3  -> 32 cols
    const uint32_t smb = smem_u32(sm);
    const int KT = K >> 6;

    const __half* Ag = A + (size_t)(bm * 128) * K;
    const __half* Bg = B + (size_t)(bn * 128) * K;

    auto issue = [&](int kt, int st) {
        uint32_t sa = smb + st * 32768;
#pragma unroll
        for (int j = 0; j < 8; j++) {
            int id  = tid + (j & 3) * 256;    // 0..1023
            int row = id >> 3, c = id & 7;
            uint32_t dst = sa + (j < 4 ? 0u : 16384u)
                         + (uint32_t)(row * 128 + ((c ^ (row & 7)) << 4));
            const __half* src = (j < 4 ? Ag : Bg) + (size_t)row * K + kt * 64 + c * 8;
            cp_async16(dst, src);
        }
        cp_commit();
    };

    float acc[4][4][4];
#pragma unroll
    for (int i = 0; i < 4; i++)
#pragma unroll
        for (int j = 0; j < 4; j++)
#pragma unroll
            for (int k = 0; k < 4; k++) acc[i][j][k] = 0.f;

    issue(0, 0);
    issue(1, 1);

    const int l7  = lane & 7;
    const int l8  = (lane >> 3) & 1;
    const int l16 = lane >> 4;

    uint32_t aRow[4], bRow[4];
#pragma unroll
    for (int mt = 0; mt < 4; mt++)
        aRow[mt] = (uint32_t)((wm * 64 + mt * 16 + l7 + l8 * 8) * 128);
#pragma unroll
    for (int nt = 0; nt < 4; nt++)
        bRow[nt] = (uint32_t)(16384 + (wn * 32 + nt * 8 + l7) * 128);

    for (int kt = 0; kt < KT; kt++) {
        if (kt + 1 < KT) cp_wait<1>(); else cp_wait<0>();
        __syncthreads();
        if (kt + 2 < KT) issue(kt + 2, (kt + 2) % 3);

        uint32_t st = smb + (kt % 3) * 32768;
#pragma unroll
        for (int kq = 0; kq < 4; kq++) {
            uint32_t aF[4][4], bF[4][2];
            uint32_t ach = (uint32_t)((((kq * 2 + l16) ^ l7)) << 4);
#pragma unroll
            for (int mt = 0; mt < 4; mt++)
                ldsm4(aF[mt][0], aF[mt][1], aF[mt][2], aF[mt][3],
                      st + aRow[mt] + ach);
            uint32_t bch = (uint32_t)((((kq * 2 + l8) ^ l7)) << 4);
#pragma unroll
            for (int nt = 0; nt < 4; nt++)
                ldsm2(bF[nt][0], bF[nt][1], st + bRow[nt] + bch);
#pragma unroll
            for (int mt = 0; mt < 4; mt++)
#pragma unroll
                for (int nt = 0; nt < 4; nt++)
                    mma16816(acc[mt][nt], aF[mt], bF[nt]);
        }
    }

    // epilogue
    const int gid = lane >> 2, tig = lane & 3;
#pragma unroll
    for (int mt = 0; mt < 4; mt++) {
        int row0 = bm * 128 + wm * 64 + mt * 16 + gid;
#pragma unroll
        for (int nt = 0; nt < 4; nt++) {
            int col = bn * 128 + wn * 32 + nt * 8 + tig * 2;
            float b0 = bias1 ? bias1[col] : 0.f;
            float b1 = bias1 ? bias1[col + 1] : 0.f;
            if (bias2) { b0 += bias2[col]; b1 += bias2[col + 1]; }
            *(float2*)(C + (size_t)row0 * ldc + col) =
                make_float2(acc[mt][nt][0] + b0, acc[mt][nt][1] + b1);
            *(float2*)(C + (size_t)(row0 + 8) * ldc + col) =
                make_float2(acc[mt][nt][2] + b0, acc[mt][nt][3] + b1);
        }
    }
}

// ---------------------------------------------------------------------------
// Persistent LSTM layer kernel (unchanged, verified)
// ---------------------------------------------------------------------------
__device__ __forceinline__ float sigf(float x) { return 1.f / (1.f + expf(-x)); }

__device__ __forceinline__ unsigned long long ffma2(unsigned long long a,
                                                    unsigned long long b,
                                                    unsigned long long c) {
    unsigned long long d;
    asm("fma.rn.f32x2 %0, %1, %2, %3;" : "=l"(d) : "l"(a), "l"(b), "l"(c));
    return d;
}

constexpr int SW_BYTES  = 32 * 1024 * 4;
constexpr int SH2_BYTES = KP * S2 * 8;
constexpr int SG_BYTES  = 32 * 33 * 4;
constexpr int SMEM_LSTM = SW_BYTES + SH2_BYTES + SG_BYTES;

__global__ __launch_bounds__(NTHR, 1)
void lstm_persist(const float* __restrict__ xproj,
                  const float* __restrict__ Whh,
                  const float* __restrict__ h0l,
                  const float* __restrict__ c0l,
                  float* __restrict__ y,
                  float* __restrict__ hs_out,
                  float* __restrict__ cs_out) {
    extern __shared__ char smem_raw[];
    float*              sw  = (float*)smem_raw;
    unsigned long long* sh2 = (unsigned long long*)(smem_raw + SW_BYTES);
    float*              sg  = (float*)(smem_raw + SW_BYTES + SH2_BYTES);

    const int tid  = threadIdx.x;
    const int blk  = blockIdx.x;
    const int n0   = blk * 8;
    const int wrp  = tid >> 5;
    const int lane = tid & 31;
    const int b2   = tid >> 3;
    const int u2   = tid & 7;

    for (int i = tid; i < 32 * 256; i += NTHR) {
        int r   = i >> 8;
        int k4  = (i & 255) * 4;
        int gr  = ((r >> 3) * H_) + n0 + (r & 7);
        *(float4*)&sw[r * 1024 + k4] = *(const float4*)&Whh[(size_t)gr * H_ + k4];
    }

    __shared__ unsigned s_base;
    if (tid == 0) s_base = g_gen;

    float c_reg = c0l[b2 * H_ + n0 + u2];

    __syncthreads();
    const unsigned base = s_base;

    for (int t = 0; t < T_; ++t) {
        const float* hp = t ? (y + (size_t)(t - 1) * B_ * H_) : h0l;

        float4 pf[8];
#pragma unroll
        for (int i = 0; i < 8; i++) {
            int id = tid + i * NTHR;
            int b  = id >> 6, k4 = id & 63;
            pf[i] = __ldcg((const float4*)(hp + (size_t)b * H_) + k4);
        }

        unsigned long long acc[4] = {0ull, 0ull, 0ull, 0ull};

        for (int c = 0; c < 4; ++c) {
#pragma unroll
            for (int i = 0; i < 8; i++) {
                int id = tid + i * NTHR;
                int b  = id >> 6, k4 = id & 63;
                int p  = k4 * 2;
                sh2[(size_t)p * S2 + b]       = *(unsigned long long*)&pf[i].x;
                sh2[(size_t)(p + 1) * S2 + b] = *(unsigned long long*)&pf[i].z;
            }
            __syncthreads();

            if (c < 3) {
                int k0n = (c + 1) * KC;
#pragma unroll
                for (int i = 0; i < 8; i++) {
                    int id = tid + i * NTHR;
                    int b  = id >> 6, k4 = id & 63;
                    pf[i] = __ldcg((const float4*)(hp + (size_t)b * H_ + k0n) + k4);
                }
            }

            const float* wbase = sw + (wrp * 4) * 1024 + c * KC;
            const unsigned long long* hb = sh2 + lane;
#pragma unroll 4
            for (int p = 0; p < KP; p += 2) {
                unsigned long long h01 = hb[(size_t)p * S2];
                unsigned long long h23 = hb[(size_t)(p + 1) * S2];
#pragma unroll
                for (int j = 0; j < 4; j++) {
                    double2 wv = *(const double2*)(wbase + j * 1024 + p * 2);
                    acc[j] = ffma2(__double_as_longlong(wv.x), h01, acc[j]);
                    acc[j] = ffma2(__double_as_longlong(wv.y), h23, acc[j]);
                }
            }
            __syncthreads();
        }

#pragma unroll
        for (int j = 0; j < 4; j++) {
            union { unsigned long long u; float2 f; } cv;
            cv.u = acc[j];
            sg[(wrp * 4 + j) * 33 + lane] = cv.f.x + cv.f.y;
        }
        __syncthreads();

        const float* xp = xproj + ((size_t)t * B_ + b2) * G4H + n0 + u2;
        float gi = sg[(0 * 8 + u2) * 33 + b2] + xp[0 * H_];
        float gf = sg[(1 * 8 + u2) * 33 + b2] + xp[1 * H_];
        float gg = sg[(2 * 8 + u2) * 33 + b2] + xp[2 * H_];
        float go = sg[(3 * 8 + u2) * 33 + b2] + xp[3 * H_];

        float i = sigf(gi);
        float f = sigf(gf);
        float g = tanhf(gg);
        float o = sigf(go);
        c_reg   = f * c_reg + i * g;
        float h = o * tanhf(c_reg);

        y[(size_t)t * B_ * H_ + b2 * H_ + n0 + u2] = h;
        if (t == T_ - 1) {
            hs_out[b2 * H_ + n0 + u2] = h;
            cs_out[b2 * H_ + n0 + u2] = c_reg;
        }

        __syncthreads();
        if (tid == 0) {
            unsigned target = base + (unsigned)(t + 1);
            __threadfence();
            unsigned arr = atomicAdd(&g_cnt, 1u);
            if (arr == NBLK - 1) {
                g_cnt = 0;
                __threadfence();
                g_gen = target;
            } else {
                while ((int)(g_gen - target) < 0) { __nanosleep(32); }
            }
        }
        __syncthreads();
    }
}

// ---------------------------------------------------------------------------
// Launch
// ---------------------------------------------------------------------------
extern "C" void kernel_launch(void* const* d_in, const int* in_sizes, int n_in,
                              void* d_out, int out_size) {
    const int*   input = (const int*)d_in[0];
    const float* h0    = (const float*)d_in[1];
    const float* c0    = (const float*)d_in[2];
    const float* emb   = (const float*)d_in[3];
    const float* W_ih  = (const float*)d_in[4];
    const float* W_hh  = (const float*)d_in[5];
    const float* b_ih  = (const float*)d_in[6];
    const float* b_hh  = (const float*)d_in[7];
    const float* dec_W = (const float*)d_in[8];
    const float* dec_b = (const float*)d_in[9];
    float* out = (float*)d_out;

    void* p;
    cudaGetSymbolAddress(&p, g_xb0);    float* xb0 = (float*)p;
    cudaGetSymbolAddress(&p, g_xb1);    float* xb1 = (float*)p;
    cudaGetSymbolAddress(&p, g_xproj);  float* xproj = (float*)p;
    cudaGetSymbolAddress(&p, g_auga);   __half* auga = (__half*)p;
    cudaGetSymbolAddress(&p, g_augwih); __half* augwih = (__half*)p;
    cudaGetSymbolAddress(&p, g_augdec); __half* augdec = (__half*)p;

    cudaFuncSetAttribute(lstm_persist,
                         cudaFuncAttributeMaxDynamicSharedMemorySize, SMEM_LSTM);
    cudaFuncSetAttribute(gemm_fp16_mma,
                         cudaFuncAttributeMaxDynamicSharedMemorySize, GEMM_SMEM);

    // 1) embedding + weight augmentations
    embed_kernel<<<TB, 256>>>(input, emb, xb0);
    augh_kernel<<<V_, 256>>>(dec_W, augdec, 1);                      // [hi|hi]
    augh_kernel<<<G4H, 256>>>(W_ih, augwih, 3);                      // [hi|lo|hi]
    augh_kernel<<<G4H, 256>>>(W_ih + (size_t)G4H * E_,
                              augwih + (size_t)G4H * K3, 3);

    const size_t D0 = (size_t)TB * V_;
    const size_t BH = (size_t)B_ * H_;

    for (int l = 0; l < L_; ++l) {
        const float* xin = l ? xb1 : xb0;
        float*       y   = l ? xb0 : xb1;

        // 2) activation augmentation + fp16 tensor-core input projection
        augh_kernel<<<TB, 256>>>(xin, auga, 2);                      // [hi|hi|lo]
        gemm_fp16_mma<<<(G4H / 128) * 32, 256, GEMM_SMEM>>>(
            auga, augwih + (size_t)l * G4H * K3,
            b_ih + (size_t)l * G4H, b_hh + (size_t)l * G4H,
            xproj, K3, G4H);

        // 3) recurrence (persistent)
        lstm_persist<<<NBLK, NTHR, SMEM_LSTM>>>(
            xproj, W_hh + (size_t)l * G4H * H_,
            h0 + (size_t)l * BH, c0 + (size_t)l * BH,
            y,
            out + D0 + (size_t)l * BH,
            out + D0 + (size_t)L_ * BH + (size_t)l * BH);
    }

    // 4) decoder: 2-term fp16 split
    augh_kernel<<<TB, 256>>>(xb0, auga, 0);                          // [hi|lo]
    gemm_fp16_mma<<<(V_ / 128) * 32, 256, GEMM_SMEM>>>(
        auga, augdec, dec_b, nullptr, out, K2, V_);
}

// round 6
// speedup vs baseline: 2.9388x; 1.4050x over previous
#include <cuda_runtime.h>
#include <cuda_fp16.h>
#include <math.h>
#include <stdint.h>

// Problem constants
constexpr int T_ = 128, B_ = 32, L_ = 2, H_ = 1024, E_ = 1024, V_ = 32000;
constexpr int TB  = T_ * B_;     // 4096
constexpr int G4H = 4 * H_;      // 4096

constexpr int NBLK = 128;        // persistent blocks (LSTM), 8 units each

// fp16 GEMM constants
constexpr int K2 = 2048;         // 2-term augmented K (decoder)
constexpr int K3 = 3072;         // 3-term augmented K (xproj)
constexpr int GEMM_SMEM = 3 * 32768;

// LSTM smem: W (2 seg x 16 chunk x 4KB) + 4 h slots x 8KB
constexpr int LSTM_SMEM = 2 * 16 * 4096 + 4 * 8192;   // 163840

// Scratch (device globals)
__device__ float g_xb0[TB * E_];
__device__ float g_xb1[TB * H_];
__device__ float g_xproj[TB * G4H];
__device__ alignas(256) __half g_auga[(size_t)TB * K3];          // 25MB
__device__ alignas(256) __half g_augwih[(size_t)L_ * G4H * K3];  // 50MB
__device__ alignas(256) __half g_augdec[(size_t)V_ * K2];        // 131MB
__device__ alignas(256) __half g_whhaug[(size_t)L_ * 2 * G4H * H_]; // 32MB
__device__ alignas(256) __half g_haug[2 * 2 * B_ * H_];          // parity x seg

// barrier state
__device__ volatile unsigned g_gen;
__device__ unsigned g_flags[NBLK * 32];   // 128B-padded per-block flags

// ---------------------------------------------------------------------------
// Embedding gather
// ---------------------------------------------------------------------------
__global__ void embed_kernel(const int* __restrict__ idx,
                             const float* __restrict__ emb,
                             float* __restrict__ out) {
    int tb = blockIdx.x;
    int v  = idx[tb];
    const float4* src = (const float4*)(emb + (size_t)v * E_);
    float4*       dst = (float4*)(out + (size_t)tb * E_);
    dst[threadIdx.x] = src[threadIdx.x];
}

// ---------------------------------------------------------------------------
// fp16 hi/lo augmentation (GEMM operands)
// mode 0 (A 2-term): [hi|lo]   mode 1 (B 2-term): [hi|hi]
// mode 2 (A 3-term): [hi|hi|lo]   mode 3 (B 3-term): [hi|lo|hi]
// ---------------------------------------------------------------------------
__global__ void augh_kernel(const float* __restrict__ in,
                            __half* __restrict__ out, int mode) {
    const int nseg   = (mode >= 2) ? 3 : 2;
    const int stride = nseg * 1024;
    int r  = blockIdx.x;
    int k4 = threadIdx.x << 2;
    float4 x = *(const float4*)(in + (size_t)r * 1024 + k4);

    float xs[4] = {x.x, x.y, x.z, x.w};
    __half h[4], l[4];
#pragma unroll
    for (int j = 0; j < 4; j++) {
        h[j] = __float2half_rn(xs[j]);
        l[j] = __float2half_rn(xs[j] - __half2float(h[j]));
    }
    unsigned long long hv, lv;
    {
        unsigned short* hp = (unsigned short*)&hv;
        unsigned short* lp = (unsigned short*)&lv;
#pragma unroll
        for (int j = 0; j < 4; j++) {
            hp[j] = *(unsigned short*)&h[j];
            lp[j] = *(unsigned short*)&l[j];
        }
    }
    __half* base = out + (size_t)r * stride + k4;
    *(unsigned long long*)(base) = hv;
    unsigned long long s1 = (mode == 0 || mode == 3) ? lv : hv;
    *(unsigned long long*)(base + 1024) = s1;
    if (nseg == 3) {
        unsigned long long s2 = (mode == 2) ? lv : hv;
        *(unsigned long long*)(base + 2048) = s2;
    }
}

// W_hh split: fp32 [L*4H][1024] -> fp16 planes [L][2][4H][1024]
__global__ void whh_aug_kernel(const float* __restrict__ Whh,
                               __half* __restrict__ out) {
    int row = blockIdx.x;            // 0..L*4H-1
    int l = row >> 12, r = row & 4095;
    int k = threadIdx.x << 2;
    float4 v = *(const float4*)(Whh + (size_t)row * 1024 + k);
    float xs[4] = {v.x, v.y, v.z, v.w};
    __half h[4], lo[4];
#pragma unroll
    for (int j = 0; j < 4; j++) {
        h[j]  = __float2half_rn(xs[j]);
        lo[j] = __float2half_rn(xs[j] - __half2float(h[j]));
    }
    unsigned long long hv, lv;
    unsigned short* hp = (unsigned short*)&hv;
    unsigned short* lp = (unsigned short*)&lv;
#pragma unroll
    for (int j = 0; j < 4; j++) {
        hp[j] = *(unsigned short*)&h[j];
        lp[j] = *(unsigned short*)&lo[j];
    }
    size_t lb = (size_t)l * 2 * G4H * H_;
    *(unsigned long long*)(out + lb + (size_t)r * 1024 + k) = hv;
    *(unsigned long long*)(out + lb + (size_t)G4H * H_ + (size_t)r * 1024 + k) = lv;
}

// h0 split into parity-0 haug buffers
__global__ void h0_aug_kernel(const float* __restrict__ h0l,
                              __half* __restrict__ haug) {
    int b = blockIdx.x;
    int k = threadIdx.x << 2;
    float4 v = *(const float4*)(h0l + (size_t)b * H_ + k);
    float xs[4] = {v.x, v.y, v.z, v.w};
    __half h[4], lo[4];
#pragma unroll
    for (int j = 0; j < 4; j++) {
        h[j]  = __float2half_rn(xs[j]);
        lo[j] = __float2half_rn(xs[j] - __half2float(h[j]));
    }
    unsigned long long hv, lv;
    unsigned short* hp = (unsigned short*)&hv;
    unsigned short* lp = (unsigned short*)&lv;
#pragma unroll
    for (int j = 0; j < 4; j++) {
        hp[j] = *(unsigned short*)&h[j];
        lp[j] = *(unsigned short*)&lo[j];
    }
    *(unsigned long long*)(haug + (size_t)b * H_ + k) = hv;                 // seg hi
    *(unsigned long long*)(haug + (size_t)B_ * H_ + (size_t)b * H_ + k) = lv; // seg lo
}

// ---------------------------------------------------------------------------
// low-level helpers
// ---------------------------------------------------------------------------
__device__ __forceinline__ uint32_t smem_u32(const void* p) {
    uint32_t a;
    asm("{ .reg .u64 t; cvta.to.shared.u64 t, %1; cvt.u32.u64 %0, t; }"
        : "=r"(a) : "l"(p));
    return a;
}
__device__ __forceinline__ void cp_async16(uint32_t saddr, const void* gptr) {
    asm volatile("cp.async.cg.shared.global [%0], [%1], 16;\n"
                 :: "r"(saddr), "l"(gptr));
}
__device__ __forceinline__ void cp_commit() {
    asm volatile("cp.async.commit_group;\n");
}
template <int N>
__device__ __forceinline__ void cp_wait() {
    asm volatile("cp.async.wait_group %0;\n" :: "n"(N));
}
__device__ __forceinline__ void ldsm4a(uint32_t* r, uint32_t a) {
    asm volatile("ldmatrix.sync.aligned.m8n8.x4.shared.b16 {%0,%1,%2,%3},[%4];"
                 : "=r"(r[0]), "=r"(r[1]), "=r"(r[2]), "=r"(r[3]) : "r"(a));
}
__device__ __forceinline__ void ldsm2(uint32_t& r0, uint32_t& r1, uint32_t a) {
    asm volatile("ldmatrix.sync.aligned.m8n8.x2.shared.b16 {%0,%1},[%2];"
                 : "=r"(r0), "=r"(r1) : "r"(a));
}
__device__ __forceinline__ void mma16816(float* c, const uint32_t* a,
                                         uint32_t b0, uint32_t b1) {
    asm volatile(
        "mma.sync.aligned.m16n8k16.row.col.f32.f16.f16.f32 "
        "{%0,%1,%2,%3},{%4,%5,%6,%7},{%8,%9},{%0,%1,%2,%3};"
        : "+f"(c[0]), "+f"(c[1]), "+f"(c[2]), "+f"(c[3])
        : "r"(a[0]), "r"(a[1]), "r"(a[2]), "r"(a[3]), "r"(b0), "r"(b1));
}
__device__ __forceinline__ float sigf(float x) { return 1.f / (1.f + expf(-x)); }

// ---------------------------------------------------------------------------
// fp16 mma.sync GEMM (unchanged from R5): C = A @ B^T + bias1 + bias2
// ---------------------------------------------------------------------------
__global__ __launch_bounds__(256, 2)
void gemm_fp16_mma(const __half* __restrict__ A, const __half* __restrict__ B,
                   const float* __restrict__ bias1, const float* __restrict__ bias2,
                   float* __restrict__ C, int K, int ldc) {
    extern __shared__ char sm[];
    const int tid  = threadIdx.x;
    const int lane = tid & 31;
    const int wid  = tid >> 5;
    const int bm   = blockIdx.x & 31;
    const int bn   = blockIdx.x >> 5;
    const int wm   = wid >> 2;
    const int wn   = wid & 3;
    const uint32_t smb = smem_u32(sm);
    const int KT = K >> 6;

    const __half* Ag = A + (size_t)(bm * 128) * K;
    const __half* Bg = B + (size_t)(bn * 128) * K;

    auto issue = [&](int kt, int st) {
        uint32_t sa = smb + st * 32768;
#pragma unroll
        for (int j = 0; j < 8; j++) {
            int id  = tid + (j & 3) * 256;
            int row = id >> 3, c = id & 7;
            uint32_t dst = sa + (j < 4 ? 0u : 16384u)
                         + (uint32_t)(row * 128 + ((c ^ (row & 7)) << 4));
            const __half* src = (j < 4 ? Ag : Bg) + (size_t)row * K + kt * 64 + c * 8;
            cp_async16(dst, src);
        }
        cp_commit();
    };

    float acc[4][4][4];
#pragma unroll
    for (int i = 0; i < 4; i++)
#pragma unroll
        for (int j = 0; j < 4; j++)
#pragma unroll
            for (int k = 0; k < 4; k++) acc[i][j][k] = 0.f;

    issue(0, 0);
    issue(1, 1);

    const int l7  = lane & 7;
    const int l8  = (lane >> 3) & 1;
    const int l16 = lane >> 4;

    uint32_t aRow[4], bRow[4];
#pragma unroll
    for (int mt = 0; mt < 4; mt++)
        aRow[mt] = (uint32_t)((wm * 64 + mt * 16 + l7 + l8 * 8) * 128);
#pragma unroll
    for (int nt = 0; nt < 4; nt++)
        bRow[nt] = (uint32_t)(16384 + (wn * 32 + nt * 8 + l7) * 128);

    for (int kt = 0; kt < KT; kt++) {
        if (kt + 1 < KT) cp_wait<1>(); else cp_wait<0>();
        __syncthreads();
        if (kt + 2 < KT) issue(kt + 2, (kt + 2) % 3);

        uint32_t st = smb + (kt % 3) * 32768;
#pragma unroll
        for (int kq = 0; kq < 4; kq++) {
            uint32_t aF[4][4], bF[4][2];
            uint32_t ach = (uint32_t)((((kq * 2 + l16) ^ l7)) << 4);
#pragma unroll
            for (int mt = 0; mt < 4; mt++)
                ldsm4a(aF[mt], st + aRow[mt] + ach);
            uint32_t bch = (uint32_t)((((kq * 2 + l8) ^ l7)) << 4);
#pragma unroll
            for (int nt = 0; nt < 4; nt++)
                ldsm2(bF[nt][0], bF[nt][1], st + bRow[nt] + bch);
#pragma unroll
            for (int mt = 0; mt < 4; mt++)
#pragma unroll
                for (int nt = 0; nt < 4; nt++)
                    mma16816(acc[mt][nt], aF[mt], bF[nt][0], bF[nt][1]);
        }
    }

    const int gid = lane >> 2, tig = lane & 3;
#pragma unroll
    for (int mt = 0; mt < 4; mt++) {
        int row0 = bm * 128 + wm * 64 + mt * 16 + gid;
#pragma unroll
        for (int nt = 0; nt < 4; nt++) {
            int col = bn * 128 + wn * 32 + nt * 8 + tig * 2;
            float b0 = bias1 ? bias1[col] : 0.f;
            float b1 = bias1 ? bias1[col + 1] : 0.f;
            if (bias2) { b0 += bias2[col]; b1 += bias2[col + 1]; }
            *(float2*)(C + (size_t)row0 * ldc + col) =
                make_float2(acc[mt][nt][0] + b0, acc[mt][nt][1] + b1);
            *(float2*)(C + (size_t)(row0 + 8) * ldc + col) =
                make_float2(acc[mt][nt][2] + b0, acc[mt][nt][3] + b1);
        }
    }
}

// ---------------------------------------------------------------------------
// Persistent LSTM with mma.sync recurrence
// Block = 8 units (32 W rows). gates[32b x 32r] = h_aug @ W_aug^T, 3-term split.
// ---------------------------------------------------------------------------
__global__ __launch_bounds__(256, 1)
void lstm_mma(const float* __restrict__ xproj,     // [T*B][4H]
              const __half* __restrict__ whhaug,   // [2][4H][1024] for this layer
              const float* __restrict__ c0l,       // [B][H]
              float* __restrict__ y,               // [T][B][H]
              __half* __restrict__ haug,           // [2 parity][2 seg][B][1024]
              float* __restrict__ hs_out, float* __restrict__ cs_out) {
    extern __shared__ char dsm[];
    __shared__ float sg[4][32][8];
    __shared__ unsigned s_base;

    const int tid  = threadIdx.x;
    const int blk  = blockIdx.x;
    const int n0   = blk * 8;
    const int wid  = tid >> 5;
    const int lane = tid & 31;
    const int l7   = lane & 7;
    const int l16  = lane >> 4;
    const int g2   = (lane >> 3) & 3;
    const int gid  = lane >> 2;
    const int tig  = lane & 3;
    const int mt   = wid >> 2;          // batch half
    const int nt   = wid & 3;           // gate
    const int b2   = tid >> 3;          // phase2 batch
    const int u2   = tid & 7;           // phase2 unit
    const uint32_t smb = smem_u32(dsm);
    const uint32_t HBASE = 131072;      // h slots base

    // load W (hi+lo) into swizzled smem chunks
    for (int idx = tid; idx < 8192; idx += 256) {
        int s   = idx >> 12;
        int rem = idx & 4095;
        int ci  = rem >> 8;
        int rr  = (rem >> 3) & 31;
        int c   = rem & 7;
        uint32_t dst = (uint32_t)(s * 65536 + ci * 4096 + rr * 128
                                  + ((c ^ (rr & 7)) << 4));
        int gr = (rr >> 3) * H_ + n0 + (rr & 7);
        const __half* src = whhaug + (size_t)s * G4H * H_ + (size_t)gr * H_
                          + ci * 64 + c * 8;
        *(float4*)(dsm + dst) = *(const float4*)src;
    }

    if (tid == 0) s_base = g_gen;
    float c_reg = c0l[b2 * H_ + n0 + u2];
    __syncthreads();
    const unsigned base = s_base;

    const uint32_t aRow128 = (uint32_t)((mt * 16 + l7 + ((lane >> 3) & 1) * 8) * 128);
    const uint32_t bRow128 = (uint32_t)((nt * 8 + l7) * 128);

    for (int t = 0; t < T_; ++t) {
        const int pR = t & 1, pW = (t + 1) & 1;
        const __half* hHi = haug + (size_t)(pR * 2 + 0) * B_ * H_;
        const __half* hLo = haug + (size_t)(pR * 2 + 1) * B_ * H_;

        // prefetch xproj gate values (independent of h)
        const float* xp = xproj + ((size_t)t * B_ + b2) * G4H + n0 + u2;
        float xpi = __ldcg(xp);
        float xpf = __ldcg(xp + H_);
        float xpg = __ldcg(xp + 2 * H_);
        float xpo = __ldcg(xp + 3 * H_);

        // slot loader: slot i (0..15): i<8 -> hHi k=i*128, else hLo k=(i-8)*128
        auto issue_slot = [&](int i) {
            const __half* src = (i < 8) ? hHi : hLo;
            int k0 = (i & 7) * 128;
            uint32_t sb = smb + HBASE + (uint32_t)((i & 3) * 8192);
            int row = tid >> 3, c = tid & 7;
            uint32_t sw = (uint32_t)(row * 128 + ((c ^ (row & 7)) << 4));
#pragma unroll
            for (int cc = 0; cc < 2; cc++)
                cp_async16(sb + cc * 4096 + sw,
                           src + (size_t)row * H_ + k0 + cc * 64 + c * 8);
            cp_commit();
        };

        float acc[4] = {0.f, 0.f, 0.f, 0.f};

        issue_slot(0); issue_slot(1); issue_slot(2);

#pragma unroll 1
        for (int i = 0; i < 16; i++) {
            if (i < 14)      cp_wait<2>();
            else if (i == 14) cp_wait<1>();
            else             cp_wait<0>();
            __syncthreads();
            if (i + 3 < 16) issue_slot(i + 3);

            uint32_t slotB = smb + HBASE + (uint32_t)((i & 3) * 8192);
            int ciBase = (i & 7) * 2;
            bool pass12 = (i < 8);
#pragma unroll
            for (int cc = 0; cc < 2; cc++) {
                int ci = ciBase + cc;
                uint32_t wHi = smb + (uint32_t)(ci * 4096);
                uint32_t wLo = wHi + 65536;
                uint32_t hC  = slotB + (uint32_t)(cc * 4096);
#pragma unroll
                for (int kq2 = 0; kq2 < 2; kq2++) {
                    uint32_t bOff = bRow128 + (uint32_t)((((kq2 * 4 + g2) ^ l7)) << 4);
                    uint32_t a0[4], a1[4], bh[4];
                    ldsm4a(bh, wHi + bOff);
                    ldsm4a(a0, hC + aRow128
                               + (uint32_t)((((kq2 * 4 + l16) ^ l7)) << 4));
                    ldsm4a(a1, hC + aRow128
                               + (uint32_t)((((kq2 * 4 + 2 + l16) ^ l7)) << 4));
                    mma16816(acc, a0, bh[0], bh[1]);
                    mma16816(acc, a1, bh[2], bh[3]);
                    if (pass12) {
                        uint32_t bl[4];
                        ldsm4a(bl, wLo + bOff);
                        mma16816(acc, a0, bl[0], bl[1]);
                        mma16816(acc, a1, bl[2], bl[3]);
                    }
                }
            }
        }

        // gates to smem: C row = batch, col = W-row (gate nt, unit tig*2)
        sg[nt][mt * 16 + gid][tig * 2]     = acc[0];
        sg[nt][mt * 16 + gid][tig * 2 + 1] = acc[1];
        sg[nt][mt * 16 + gid + 8][tig * 2]     = acc[2];
        sg[nt][mt * 16 + gid + 8][tig * 2 + 1] = acc[3];
        __syncthreads();

        // phase 2
        float gi = sg[0][b2][u2] + xpi;
        float gf = sg[1][b2][u2] + xpf;
        float gg = sg[2][b2][u2] + xpg;
        float go = sg[3][b2][u2] + xpo;
        float iv = sigf(gi), fv = sigf(gf), gv = tanhf(gg), ov = sigf(go);
        c_reg = fv * c_reg + iv * gv;
        float h = ov * tanhf(c_reg);

        y[(size_t)t * B_ * H_ + b2 * H_ + n0 + u2] = h;
        __half hh = __float2half_rn(h);
        __half hl = __float2half_rn(h - __half2float(hh));
        haug[(size_t)(pW * 2 + 0) * B_ * H_ + b2 * H_ + n0 + u2] = hh;
        haug[(size_t)(pW * 2 + 1) * B_ * H_ + b2 * H_ + n0 + u2] = hl;
        if (t == T_ - 1) {
            hs_out[b2 * H_ + n0 + u2] = h;
            cs_out[b2 * H_ + n0 + u2] = c_reg;
        }

        // grid barrier: flags + master release
        __syncthreads();
        unsigned tgt = base + (unsigned)(t + 1);
        if (tid == 0) {
            __threadfence();
            *(volatile unsigned*)&g_flags[blk * 32] = tgt;
        }
        if (blk == 0 && wid == 0) {
            volatile unsigned* fl = g_flags;
            for (;;) {
                int ok = 1;
#pragma unroll
                for (int j = 0; j < 4; j++) {
                    unsigned v = fl[(lane + 32 * j) * 32];
                    if ((int)(v - tgt) < 0) ok = 0;
                }
                if (__all_sync(0xffffffffu, ok)) break;
                __nanosleep(16);
            }
            __threadfence();
            if (lane == 0) g_gen = tgt;
        }
        if (tid == 0) {
            while ((int)(g_gen - tgt) < 0) { __nanosleep(24); }
        }
        __syncthreads();
    }
}

// ---------------------------------------------------------------------------
// Launch
// ---------------------------------------------------------------------------
extern "C" void kernel_launch(void* const* d_in, const int* in_sizes, int n_in,
                              void* d_out, int out_size) {
    const int*   input = (const int*)d_in[0];
    const float* h0    = (const float*)d_in[1];
    const float* c0    = (const float*)d_in[2];
    const float* emb   = (const float*)d_in[3];
    const float* W_ih  = (const float*)d_in[4];
    const float* W_hh  = (const float*)d_in[5];
    const float* b_ih  = (const float*)d_in[6];
    const float* b_hh  = (const float*)d_in[7];
    const float* dec_W = (const float*)d_in[8];
    const float* dec_b = (const float*)d_in[9];
    float* out = (float*)d_out;

    void* p;
    cudaGetSymbolAddress(&p, g_xb0);    float* xb0 = (float*)p;
    cudaGetSymbolAddress(&p, g_xb1);    float* xb1 = (float*)p;
    cudaGetSymbolAddress(&p, g_xproj);  float* xproj = (float*)p;
    cudaGetSymbolAddress(&p, g_auga);   __half* auga = (__half*)p;
    cudaGetSymbolAddress(&p, g_augwih); __half* augwih = (__half*)p;
    cudaGetSymbolAddress(&p, g_augdec); __half* augdec = (__half*)p;
    cudaGetSymbolAddress(&p, g_whhaug); __half* whhaug = (__half*)p;
    cudaGetSymbolAddress(&p, g_haug);   __half* haug = (__half*)p;

    cudaFuncSetAttribute(gemm_fp16_mma,
                         cudaFuncAttributeMaxDynamicSharedMemorySize, GEMM_SMEM);
    cudaFuncSetAttribute(lstm_mma,
                         cudaFuncAttributeMaxDynamicSharedMemorySize, LSTM_SMEM);

    // 1) embedding + weight augmentations
    embed_kernel<<<TB, 256>>>(input, emb, xb0);
    augh_kernel<<<V_, 256>>>(dec_W, augdec, 1);                      // [hi|hi]
    augh_kernel<<<G4H, 256>>>(W_ih, augwih, 3);                      // [hi|lo|hi]
    augh_kernel<<<G4H, 256>>>(W_ih + (size_t)G4H * E_,
                              augwih + (size_t)G4H * K3, 3);
    whh_aug_kernel<<<L_ * G4H, 256>>>(W_hh, whhaug);

    const size_t D0 = (size_t)TB * V_;
    const size_t BH = (size_t)B_ * H_;

    for (int l = 0; l < L_; ++l) {
        const float* xin = l ? xb1 : xb0;
        float*       y   = l ? xb0 : xb1;

        // 2) activation augmentation + fp16 tensor-core input projection
        augh_kernel<<<TB, 256>>>(xin, auga, 2);                      // [hi|hi|lo]
        gemm_fp16_mma<<<(G4H / 128) * 32, 256, GEMM_SMEM>>>(
            auga, augwih + (size_t)l * G4H * K3,
            b_ih + (size_t)l * G4H, b_hh + (size_t)l * G4H,
            xproj, K3, G4H);

        // 3) recurrence (persistent, mma.sync)
        h0_aug_kernel<<<B_, 256>>>(h0 + (size_t)l * BH, haug);       // parity 0
        lstm_mma<<<NBLK, 256, LSTM_SMEM>>>(
            xproj, whhaug + (size_t)l * 2 * G4H * H_,
            c0 + (size_t)l * BH, y, haug,
            out + D0 + (size_t)l * BH,
            out + D0 + (size_t)L_ * BH + (size_t)l * BH);
    }

    // 4) decoder: 2-term fp16 split
    augh_kernel<<<TB, 256>>>(xb0, auga, 0);                          // [hi|lo]
    gemm_fp16_mma<<<(V_ / 128) * 32, 256, GEMM_SMEM>>>(
        auga, augdec, dec_b, nullptr, out, K2, V_);
}

// round 8
// speedup vs baseline: 3.7576x; 1.2786x over previous
#include <cuda_runtime.h>
#include <cuda_fp16.h>
#include <math.h>
#include <stdint.h>

// Problem constants
constexpr int T_ = 128, B_ = 32, L_ = 2, H_ = 1024, E_ = 1024, V_ = 32000;
constexpr int TB  = T_ * B_;     // 4096
constexpr int G4H = 4 * H_;      // 4096

constexpr int NBLK = 128;        // persistent blocks (LSTM), 8 units each

// fp16 GEMM constants
constexpr int K2 = 2048;         // 2-term augmented K (decoder)
constexpr int K3 = 3072;         // 3-term augmented K (xproj)
constexpr int GEMM_SMEM = 3 * 32768;

// LSTM smem: W (2 seg x 16 chunk x 4KB) + 4 h slots x 8KB
constexpr int LSTM_SMEM = 2 * 16 * 4096 + 4 * 8192;   // 163840

// Scratch (device globals)
__device__ float g_xb0[TB * E_];
__device__ float g_xb1[TB * H_];
__device__ float g_xproj[TB * G4H];
__device__ alignas(256) __half g_auga[(size_t)TB * K3];          // 25MB
__device__ alignas(256) __half g_augwih[(size_t)L_ * G4H * K3];  // 50MB
__device__ alignas(256) __half g_augdec[(size_t)V_ * K2];        // 131MB
__device__ alignas(256) __half g_whhaug[(size_t)L_ * 2 * G4H * H_]; // 32MB
__device__ alignas(256) __half g_haug[2 * B_ * H_];              // parity x [B][H] hi

// barrier state: padded per-block monotonic flags
__device__ unsigned g_flags[NBLK * 32];

// ---------------------------------------------------------------------------
// Embedding gather
// ---------------------------------------------------------------------------
__global__ void embed_kernel(const int* __restrict__ idx,
                             const float* __restrict__ emb,
                             float* __restrict__ out) {
    int tb = blockIdx.x;
    int v  = idx[tb];
    const float4* src = (const float4*)(emb + (size_t)v * E_);
    float4*       dst = (float4*)(out + (size_t)tb * E_);
    dst[threadIdx.x] = src[threadIdx.x];
}

// ---------------------------------------------------------------------------
// fp16 hi/lo augmentation (GEMM operands)
// mode 0 (A 2-term): [hi|lo]   mode 1 (B 2-term): [hi|hi]
// mode 2 (A 3-term): [hi|hi|lo]   mode 3 (B 3-term): [hi|lo|hi]
// ---------------------------------------------------------------------------
__global__ void augh_kernel(const float* __restrict__ in,
                            __half* __restrict__ out, int mode) {
    const int nseg   = (mode >= 2) ? 3 : 2;
    const int stride = nseg * 1024;
    int r  = blockIdx.x;
    int k4 = threadIdx.x << 2;
    float4 x = *(const float4*)(in + (size_t)r * 1024 + k4);

    float xs[4] = {x.x, x.y, x.z, x.w};
    __half h[4], l[4];
#pragma unroll
    for (int j = 0; j < 4; j++) {
        h[j] = __float2half_rn(xs[j]);
        l[j] = __float2half_rn(xs[j] - __half2float(h[j]));
    }
    unsigned long long hv, lv;
    {
        unsigned short* hp = (unsigned short*)&hv;
        unsigned short* lp = (unsigned short*)&lv;
#pragma unroll
        for (int j = 0; j < 4; j++) {
            hp[j] = *(unsigned short*)&h[j];
            lp[j] = *(unsigned short*)&l[j];
        }
    }
    __half* base = out + (size_t)r * stride + k4;
    *(unsigned long long*)(base) = hv;
    unsigned long long s1 = (mode == 0 || mode == 3) ? lv : hv;
    *(unsigned long long*)(base + 1024) = s1;
    if (nseg == 3) {
        unsigned long long s2 = (mode == 2) ? lv : hv;
        *(unsigned long long*)(base + 2048) = s2;
    }
}

// W_hh split: fp32 [L*4H][1024] -> fp16 planes [L][2][4H][1024]
__global__ void whh_aug_kernel(const float* __restrict__ Whh,
                               __half* __restrict__ out) {
    int row = blockIdx.x;
    int l = row >> 12, r = row & 4095;
    int k = threadIdx.x << 2;
    float4 v = *(const float4*)(Whh + (size_t)row * 1024 + k);
    float xs[4] = {v.x, v.y, v.z, v.w};
    __half h[4], lo[4];
#pragma unroll
    for (int j = 0; j < 4; j++) {
        h[j]  = __float2half_rn(xs[j]);
        lo[j] = __float2half_rn(xs[j] - __half2float(h[j]));
    }
    unsigned long long hv, lv;
    unsigned short* hp = (unsigned short*)&hv;
    unsigned short* lp = (unsigned short*)&lv;
#pragma unroll
    for (int j = 0; j < 4; j++) {
        hp[j] = *(unsigned short*)&h[j];
        lp[j] = *(unsigned short*)&lo[j];
    }
    size_t lb = (size_t)l * 2 * G4H * H_;
    *(unsigned long long*)(out + lb + (size_t)r * 1024 + k) = hv;
    *(unsigned long long*)(out + lb + (size_t)G4H * H_ + (size_t)r * 1024 + k) = lv;
}

// h0 -> fp16 hi into parity-0 haug buffer
__global__ void h0_aug_kernel(const float* __restrict__ h0l,
                              __half* __restrict__ haug) {
    int b = blockIdx.x;
    int k = threadIdx.x << 2;
    float4 v = *(const float4*)(h0l + (size_t)b * H_ + k);
    __half h[4] = {__float2half_rn(v.x), __float2half_rn(v.y),
                   __float2half_rn(v.z), __float2half_rn(v.w)};
    unsigned long long hv;
    unsigned short* hp = (unsigned short*)&hv;
#pragma unroll
    for (int j = 0; j < 4; j++) hp[j] = *(unsigned short*)&h[j];
    *(unsigned long long*)(haug + (size_t)b * H_ + k) = hv;
}

// ---------------------------------------------------------------------------
// low-level helpers
// ---------------------------------------------------------------------------
__device__ __forceinline__ uint32_t smem_u32(const void* p) {
    uint32_t a;
    asm("{ .reg .u64 t; cvta.to.shared.u64 t, %1; cvt.u32.u64 %0, t; }"
        : "=r"(a) : "l"(p));
    return a;
}
__device__ __forceinline__ void cp_async16(uint32_t saddr, const void* gptr) {
    asm volatile("cp.async.cg.shared.global [%0], [%1], 16;\n"
                 :: "r"(saddr), "l"(gptr));
}
__device__ __forceinline__ void cp_commit() {
    asm volatile("cp.async.commit_group;\n");
}
template <int N>
__device__ __forceinline__ void cp_wait() {
    asm volatile("cp.async.wait_group %0;\n" :: "n"(N));
}
__device__ __forceinline__ void ldsm4a(uint32_t* r, uint32_t a) {
    asm volatile("ldmatrix.sync.aligned.m8n8.x4.shared.b16 {%0,%1,%2,%3},[%4];"
                 : "=r"(r[0]), "=r"(r[1]), "=r"(r[2]), "=r"(r[3]) : "r"(a));
}
__device__ __forceinline__ void ldsm2(uint32_t& r0, uint32_t& r1, uint32_t a) {
    asm volatile("ldmatrix.sync.aligned.m8n8.x2.shared.b16 {%0,%1},[%2];"
                 : "=r"(r0), "=r"(r1) : "r"(a));
}
__device__ __forceinline__ void mma16816(float* c, const uint32_t* a,
                                         uint32_t b0, uint32_t b1) {
    asm volatile(
        "mma.sync.aligned.m16n8k16.row.col.f32.f16.f16.f32 "
        "{%0,%1,%2,%3},{%4,%5,%6,%7},{%8,%9},{%0,%1,%2,%3};"
        : "+f"(c[0]), "+f"(c[1]), "+f"(c[2]), "+f"(c[3])
        : "r"(a[0]), "r"(a[1]), "r"(a[2]), "r"(a[3]), "r"(b0), "r"(b1));
}
__device__ __forceinline__ float sigf(float x) { return 1.f / (1.f + expf(-x)); }

// ---------------------------------------------------------------------------
// fp16 mma.sync GEMM (unchanged): C = A @ B^T + bias1 + bias2
// ---------------------------------------------------------------------------
__global__ __launch_bounds__(256, 2)
void gemm_fp16_mma(const __half* __restrict__ A, const __half* __restrict__ B,
                   const float* __restrict__ bias1, const float* __restrict__ bias2,
                   float* __restrict__ C, int K, int ldc) {
    extern __shared__ char sm[];
    const int tid  = threadIdx.x;
    const int lane = tid & 31;
    const int wid  = tid >> 5;
    const int bm   = blockIdx.x & 31;
    const int bn   = blockIdx.x >> 5;
    const int wm   = wid >> 2;
    const int wn   = wid & 3;
    const uint32_t smb = smem_u32(sm);
    const int KT = K >> 6;

    const __half* Ag = A + (size_t)(bm * 128) * K;
    const __half* Bg = B + (size_t)(bn * 128) * K;

    auto issue = [&](int kt, int st) {
        uint32_t sa = smb + st * 32768;
#pragma unroll
        for (int j = 0; j < 8; j++) {
            int id  = tid + (j & 3) * 256;
            int row = id >> 3, c = id & 7;
            uint32_t dst = sa + (j < 4 ? 0u : 16384u)
                         + (uint32_t)(row * 128 + ((c ^ (row & 7)) << 4));
            const __half* src = (j < 4 ? Ag : Bg) + (size_t)row * K + kt * 64 + c * 8;
            cp_async16(dst, src);
        }
        cp_commit();
    };

    float acc[4][4][4];
#pragma unroll
    for (int i = 0; i < 4; i++)
#pragma unroll
        for (int j = 0; j < 4; j++)
#pragma unroll
            for (int k = 0; k < 4; k++) acc[i][j][k] = 0.f;

    issue(0, 0);
    issue(1, 1);

    const int l7  = lane & 7;
    const int l8  = (lane >> 3) & 1;
    const int l16 = lane >> 4;

    uint32_t aRow[4], bRow[4];
#pragma unroll
    for (int mt = 0; mt < 4; mt++)
        aRow[mt] = (uint32_t)((wm * 64 + mt * 16 + l7 + l8 * 8) * 128);
#pragma unroll
    for (int nt = 0; nt < 4; nt++)
        bRow[nt] = (uint32_t)(16384 + (wn * 32 + nt * 8 + l7) * 128);

    for (int kt = 0; kt < KT; kt++) {
        if (kt + 1 < KT) cp_wait<1>(); else cp_wait<0>();
        __syncthreads();
        if (kt + 2 < KT) issue(kt + 2, (kt + 2) % 3);

        uint32_t st = smb + (kt % 3) * 32768;
#pragma unroll
        for (int kq = 0; kq < 4; kq++) {
            uint32_t aF[4][4], bF[4][2];
            uint32_t ach = (uint32_t)((((kq * 2 + l16) ^ l7)) << 4);
#pragma unroll
            for (int mt = 0; mt < 4; mt++)
                ldsm4a(aF[mt], st + aRow[mt] + ach);
            uint32_t bch = (uint32_t)((((kq * 2 + l8) ^ l7)) << 4);
#pragma unroll
            for (int nt = 0; nt < 4; nt++)
                ldsm2(bF[nt][0], bF[nt][1], st + bRow[nt] + bch);
#pragma unroll
            for (int mt = 0; mt < 4; mt++)
#pragma unroll
                for (int nt = 0; nt < 4; nt++)
                    mma16816(acc[mt][nt], aF[mt], bF[nt][0], bF[nt][1]);
        }
    }

    const int gid = lane >> 2, tig = lane & 3;
#pragma unroll
    for (int mt = 0; mt < 4; mt++) {
        int row0 = bm * 128 + wm * 64 + mt * 16 + gid;
#pragma unroll
        for (int nt = 0; nt < 4; nt++) {
            int col = bn * 128 + wn * 32 + nt * 8 + tig * 2;
            float b0 = bias1 ? bias1[col] : 0.f;
            float b1 = bias1 ? bias1[col + 1] : 0.f;
            if (bias2) { b0 += bias2[col]; b1 += bias2[col + 1]; }
            *(float2*)(C + (size_t)row0 * ldc + col) =
                make_float2(acc[mt][nt][0] + b0, acc[mt][nt][1] + b1);
            *(float2*)(C + (size_t)(row0 + 8) * ldc + col) =
                make_float2(acc[mt][nt][2] + b0, acc[mt][nt][3] + b1);
        }
    }
}

// ---------------------------------------------------------------------------
// Persistent LSTM with mma.sync recurrence
// gates = h_hi @ (W_hi + W_lo)^T  (h_lo term dropped; see error analysis)
// Block = 8 units (32 W rows), 8 h slots of k=128 each, 4-slot ring.
// Barrier: distributed flag all-poll (single round trip).
// ---------------------------------------------------------------------------
__global__ __launch_bounds__(256, 1)
void lstm_mma(const float* __restrict__ xproj,     // [T*B][4H]
              const __half* __restrict__ whhaug,   // [2][4H][1024] this layer
              const float* __restrict__ c0l,       // [B][H]
              float* __restrict__ y,               // [T][B][H]
              __half* __restrict__ haug,           // [2 parity][B][H] hi
              float* __restrict__ hs_out, float* __restrict__ cs_out) {
    extern __shared__ char dsm[];
    __shared__ float sg[4][32][8];
    __shared__ unsigned s_base;

    const int tid  = threadIdx.x;
    const int blk  = blockIdx.x;
    const int n0   = blk * 8;
    const int wid  = tid >> 5;
    const int lane = tid & 31;
    const int l7   = lane & 7;
    const int l16  = lane >> 4;
    const int g2   = (lane >> 3) & 3;
    const int gid  = lane >> 2;
    const int tig  = lane & 3;
    const int mt   = wid >> 2;          // batch half
    const int nt   = wid & 3;           // gate
    const int b2   = tid >> 3;          // phase2 batch
    const int u2   = tid & 7;           // phase2 unit
    const uint32_t smb = smem_u32(dsm);
    const uint32_t HBASE = 131072;      // h slot ring base

    // load W (hi+lo) into swizzled smem chunks
    for (int idx = tid; idx < 8192; idx += 256) {
        int s   = idx >> 12;
        int rem = idx & 4095;
        int ci  = rem >> 8;
        int rr  = (rem >> 3) & 31;
        int c   = rem & 7;
        uint32_t dst = (uint32_t)(s * 65536 + ci * 4096 + rr * 128
                                  + ((c ^ (rr & 7)) << 4));
        int gr = (rr >> 3) * H_ + n0 + (rr & 7);
        const __half* src = whhaug + (size_t)s * G4H * H_ + (size_t)gr * H_
                          + ci * 64 + c * 8;
        *(float4*)(dsm + dst) = *(const float4*)src;
    }

    if (tid == 0) s_base = *(volatile unsigned*)&g_flags[blk * 32];
    float c_reg = c0l[b2 * H_ + n0 + u2];
    __syncthreads();
    const unsigned base = s_base;

    const uint32_t aRow128 = (uint32_t)((mt * 16 + l7 + ((lane >> 3) & 1) * 8) * 128);
    const uint32_t bRow128 = (uint32_t)((nt * 8 + l7) * 128);

    for (int t = 0; t < T_; ++t) {
        const int pR = t & 1, pW = (t + 1) & 1;
        const __half* hHi = haug + (size_t)pR * B_ * H_;

        // prefetch xproj gate values (independent of h)
        const float* xp = xproj + ((size_t)t * B_ + b2) * G4H + n0 + u2;
        float xpi = __ldcg(xp);
        float xpf = __ldcg(xp + H_);
        float xpg = __ldcg(xp + 2 * H_);
        float xpo = __ldcg(xp + 3 * H_);

        // slot loader: slot i covers k = i*128 .. i*128+127 of h_hi
        auto issue_slot = [&](int i) {
            int k0 = i * 128;
            uint32_t sb = smb + HBASE + (uint32_t)((i & 3) * 8192);
            int row = tid >> 3, c = tid & 7;
            uint32_t sw = (uint32_t)(row * 128 + ((c ^ (row & 7)) << 4));
#pragma unroll
            for (int cc = 0; cc < 2; cc++)
                cp_async16(sb + cc * 4096 + sw,
                           hHi + (size_t)row * H_ + k0 + cc * 64 + c * 8);
            cp_commit();
        };

        float acc[4] = {0.f, 0.f, 0.f, 0.f};

        issue_slot(0); issue_slot(1); issue_slot(2);

#pragma unroll 1
        for (int i = 0; i < 8; i++) {
            if (i < 6)       cp_wait<2>();
            else if (i == 6) cp_wait<1>();
            else             cp_wait<0>();
            __syncthreads();
            if (i + 3 < 8) issue_slot(i + 3);

            uint32_t slotB = smb + HBASE + (uint32_t)((i & 3) * 8192);
            int ciBase = i * 2;
#pragma unroll
            for (int cc = 0; cc < 2; cc++) {
                int ci = ciBase + cc;
                uint32_t wHi = smb + (uint32_t)(ci * 4096);
                uint32_t wLo = wHi + 65536;
                uint32_t hC  = slotB + (uint32_t)(cc * 4096);
#pragma unroll
                for (int kq2 = 0; kq2 < 2; kq2++) {
                    uint32_t bOff = bRow128 + (uint32_t)((((kq2 * 4 + g2) ^ l7)) << 4);
                    uint32_t a0[4], a1[4], bh[4], bl[4];
                    ldsm4a(bh, wHi + bOff);
                    ldsm4a(a0, hC + aRow128
                               + (uint32_t)((((kq2 * 4 + l16) ^ l7)) << 4));
                    ldsm4a(a1, hC + aRow128
                               + (uint32_t)((((kq2 * 4 + 2 + l16) ^ l7)) << 4));
                    mma16816(acc, a0, bh[0], bh[1]);
                    mma16816(acc, a1, bh[2], bh[3]);
                    ldsm4a(bl, wLo + bOff);
                    mma16816(acc, a0, bl[0], bl[1]);
                    mma16816(acc, a1, bl[2], bl[3]);
                }
            }
        }

        // gates to smem: C row = batch, col = W-row (gate nt, unit tig*2)
        sg[nt][mt * 16 + gid][tig * 2]     = acc[0];
        sg[nt][mt * 16 + gid][tig * 2 + 1] = acc[1];
        sg[nt][mt * 16 + gid + 8][tig * 2]     = acc[2];
        sg[nt][mt * 16 + gid + 8][tig * 2 + 1] = acc[3];
        __syncthreads();

        // phase 2
        float gi = sg[0][b2][u2] + xpi;
        float gf = sg[1][b2][u2] + xpf;
        float gg = sg[2][b2][u2] + xpg;
        float go = sg[3][b2][u2] + xpo;
        float iv = sigf(gi), fv = sigf(gf), gv = tanhf(gg), ov = sigf(go);
        c_reg = fv * c_reg + iv * gv;
        float h = ov * tanhf(c_reg);

        y[(size_t)t * B_ * H_ + b2 * H_ + n0 + u2] = h;
        haug[(size_t)pW * B_ * H_ + b2 * H_ + n0 + u2] = __float2half_rn(h);
        if (t == T_ - 1) {
            hs_out[b2 * H_ + n0 + u2] = h;
            cs_out[b2 * H_ + n0 + u2] = c_reg;
        }

        // distributed barrier: publish own flag, all blocks poll all flags
        __syncthreads();
        unsigned tgt = base + (unsigned)(t + 1);
        if (tid == 0) {
            __threadfence();
            *(volatile unsigned*)&g_flags[blk * 32] = tgt;
        }
        if (wid == 0) {
            volatile unsigned* fl = g_flags;
            for (;;) {
                int ok = 1;
#pragma unroll
                for (int j = 0; j < 4; j++) {
                    unsigned v = fl[(lane + 32 * j) * 32];
                    if ((int)(v - tgt) < 0) ok = 0;
                }
                if (__all_sync(0xffffffffu, ok)) break;
                __nanosleep(16);
            }
            __threadfence();
        }
        __syncthreads();
    }
}

// ---------------------------------------------------------------------------
// Launch
// ---------------------------------------------------------------------------
extern "C" void kernel_launch(void* const* d_in, const int* in_sizes, int n_in,
                              void* d_out, int out_size) {
    const int*   input = (const int*)d_in[0];
    const float* h0    = (const float*)d_in[1];
    const float* c0    = (const float*)d_in[2];
    const float* emb   = (const float*)d_in[3];
    const float* W_ih  = (const float*)d_in[4];
    const float* W_hh  = (const float*)d_in[5];
    const float* b_ih  = (const float*)d_in[6];
    const float* b_hh  = (const float*)d_in[7];
    const float* dec_W = (const float*)d_in[8];
    const float* dec_b = (const float*)d_in[9];
    float* out = (float*)d_out;

    void* p;
    cudaGetSymbolAddress(&p, g_xb0);    float* xb0 = (float*)p;
    cudaGetSymbolAddress(&p, g_xb1);    float* xb1 = (float*)p;
    cudaGetSymbolAddress(&p, g_xproj);  float* xproj = (float*)p;
    cudaGetSymbolAddress(&p, g_auga);   __half* auga = (__half*)p;
    cudaGetSymbolAddress(&p, g_augwih); __half* augwih = (__half*)p;
    cudaGetSymbolAddress(&p, g_augdec); __half* augdec = (__half*)p;
    cudaGetSymbolAddress(&p, g_whhaug); __half* whhaug = (__half*)p;
    cudaGetSymbolAddress(&p, g_haug);   __half* haug = (__half*)p;

    cudaFuncSetAttribute(gemm_fp16_mma,
                         cudaFuncAttributeMaxDynamicSharedMemorySize, GEMM_SMEM);
    cudaFuncSetAttribute(lstm_mma,
                         cudaFuncAttributeMaxDynamicSharedMemorySize, LSTM_SMEM);

    // 1) embedding + weight augmentations
    embed_kernel<<<TB, 256>>>(input, emb, xb0);
    augh_kernel<<<V_, 256>>>(dec_W, augdec, 1);                      // [hi|hi]
    augh_kernel<<<G4H, 256>>>(W_ih, augwih, 3);                      // [hi|lo|hi]
    augh_kernel<<<G4H, 256>>>(W_ih + (size_t)G4H * E_,
                              augwih + (size_t)G4H * K3, 3);
    whh_aug_kernel<<<L_ * G4H, 256>>>(W_hh, whhaug);

    const size_t D0 = (size_t)TB * V_;
    const size_t BH = (size_t)B_ * H_;

    for (int l = 0; l < L_; ++l) {
        const float* xin = l ? xb1 : xb0;
        float*       y   = l ? xb0 : xb1;

        // 2) activation augmentation + fp16 tensor-core input projection
        augh_kernel<<<TB, 256>>>(xin, auga, 2);                      // [hi|hi|lo]
        gemm_fp16_mma<<<(G4H / 128) * 32, 256, GEMM_SMEM>>>(
            auga, augwih + (size_t)l * G4H * K3,
            b_ih + (size_t)l * G4H, b_hh + (size_t)l * G4H,
            xproj, K3, G4H);

        // 3) recurrence (persistent, mma.sync)
        h0_aug_kernel<<<B_, 256>>>(h0 + (size_t)l * BH, haug);       // parity 0
        lstm_mma<<<NBLK, 256, LSTM_SMEM>>>(
            xproj, whhaug + (size_t)l * 2 * G4H * H_,
            c0 + (size_t)l * BH, y, haug,
            out + D0 + (size_t)l * BH,
            out + D0 + (size_t)L_ * BH + (size_t)l * BH);
    }

    // 4) decoder: 2-term fp16 split
    augh_kernel<<<TB, 256>>>(xb0, auga, 0);                          // [hi|lo]
    gemm_fp16_mma<<<(V_ / 128) * 32, 256, GEMM_SMEM>>>(
        auga, augdec, dec_b, nullptr, out, K2, V_);
}

// round 9
// speedup vs baseline: 4.1998x; 1.1177x over previous
#include <cuda_runtime.h>
#include <cuda_fp16.h>
#include <math.h>
#include <stdint.h>

// Problem constants
constexpr int T_ = 128, B_ = 32, L_ = 2, H_ = 1024, E_ = 1024, V_ = 32000;
constexpr int TB  = T_ * B_;     // 4096
constexpr int G4H = 4 * H_;      // 4096

constexpr int NBLK = 128;        // persistent blocks (LSTM), 8 units each

// fp16 GEMM constants
constexpr int K2 = 2048;         // 2-term augmented K (all GEMMs now)
constexpr int GEMM_SMEM = 3 * 32768;

// LSTM smem: W_hi (16 chunks x 4KB) + 4 h slots x 8KB
constexpr int LSTM_SMEM = 16 * 4096 + 4 * 8192;   // 98304

// Scratch (device globals)
__device__ float g_xb0[TB * E_];
__device__ float g_xb1[TB * H_];
__device__ float g_xproj[TB * G4H];
__device__ alignas(256) __half g_auga[(size_t)TB * K2];          // 16.8MB
__device__ alignas(256) __half g_augwih[(size_t)L_ * G4H * K2];  // 33.5MB
__device__ alignas(256) __half g_augdec[(size_t)V_ * K2];        // 131MB
__device__ alignas(256) __half g_whhaug[(size_t)L_ * G4H * H_];  // 16MB (hi only)
__device__ alignas(256) __half g_haug[2 * B_ * H_];              // parity x [B][H] hi

// barrier state: padded per-block monotonic flags
__device__ unsigned g_flags[NBLK * 32];

// ---------------------------------------------------------------------------
// Embedding gather
// ---------------------------------------------------------------------------
__global__ void embed_kernel(const int* __restrict__ idx,
                             const float* __restrict__ emb,
                             float* __restrict__ out) {
    int tb = blockIdx.x;
    int v  = idx[tb];
    const float4* src = (const float4*)(emb + (size_t)v * E_);
    float4*       dst = (float4*)(out + (size_t)tb * E_);
    dst[threadIdx.x] = src[threadIdx.x];
}

// ---------------------------------------------------------------------------
// fp16 hi/lo augmentation: fp32 [rows][1024] -> fp16 [rows][2048]
// mode 0 (A): [hi|lo]   mode 1 (B): [hi|hi]
// ---------------------------------------------------------------------------
__global__ void augh_kernel(const float* __restrict__ in,
                            __half* __restrict__ out, int mode) {
    int r  = blockIdx.x;
    int k4 = threadIdx.x << 2;
    float4 x = *(const float4*)(in + (size_t)r * 1024 + k4);

    float xs[4] = {x.x, x.y, x.z, x.w};
    __half h[4], l[4];
#pragma unroll
    for (int j = 0; j < 4; j++) {
        h[j] = __float2half_rn(xs[j]);
        l[j] = __float2half_rn(xs[j] - __half2float(h[j]));
    }
    unsigned long long hv, lv;
    {
        unsigned short* hp = (unsigned short*)&hv;
        unsigned short* lp = (unsigned short*)&lv;
#pragma unroll
        for (int j = 0; j < 4; j++) {
            hp[j] = *(unsigned short*)&h[j];
            lp[j] = *(unsigned short*)&l[j];
        }
    }
    __half* base = out + (size_t)r * K2 + k4;
    *(unsigned long long*)(base)        = hv;
    *(unsigned long long*)(base + 1024) = (mode == 0) ? lv : hv;
}

// W_hh hi-plane only: fp32 [L*4H][1024] -> fp16 [L*4H][1024]
__global__ void whh_aug_kernel(const float* __restrict__ Whh,
                               __half* __restrict__ out) {
    int row = blockIdx.x;
    int k = threadIdx.x << 2;
    float4 v = *(const float4*)(Whh + (size_t)row * 1024 + k);
    __half h[4] = {__float2half_rn(v.x), __float2half_rn(v.y),
                   __float2half_rn(v.z), __float2half_rn(v.w)};
    unsigned long long hv;
    unsigned short* hp = (unsigned short*)&hv;
#pragma unroll
    for (int j = 0; j < 4; j++) hp[j] = *(unsigned short*)&h[j];
    *(unsigned long long*)(out + (size_t)row * 1024 + k) = hv;
}

// h0 -> fp16 hi into parity-0 haug buffer
__global__ void h0_aug_kernel(const float* __restrict__ h0l,
                              __half* __restrict__ haug) {
    int b = blockIdx.x;
    int k = threadIdx.x << 2;
    float4 v = *(const float4*)(h0l + (size_t)b * H_ + k);
    __half h[4] = {__float2half_rn(v.x), __float2half_rn(v.y),
                   __float2half_rn(v.z), __float2half_rn(v.w)};
    unsigned long long hv;
    unsigned short* hp = (unsigned short*)&hv;
#pragma unroll
    for (int j = 0; j < 4; j++) hp[j] = *(unsigned short*)&h[j];
    *(unsigned long long*)(haug + (size_t)b * H_ + k) = hv;
}

// ---------------------------------------------------------------------------
// low-level helpers
// ---------------------------------------------------------------------------
__device__ __forceinline__ uint32_t smem_u32(const void* p) {
    uint32_t a;
    asm("{ .reg .u64 t; cvta.to.shared.u64 t, %1; cvt.u32.u64 %0, t; }"
        : "=r"(a) : "l"(p));
    return a;
}
__device__ __forceinline__ void cp_async16(uint32_t saddr, const void* gptr) {
    asm volatile("cp.async.cg.shared.global [%0], [%1], 16;\n"
                 :: "r"(saddr), "l"(gptr));
}
__device__ __forceinline__ void cp_commit() {
    asm volatile("cp.async.commit_group;\n");
}
template <int N>
__device__ __forceinline__ void cp_wait() {
    asm volatile("cp.async.wait_group %0;\n" :: "n"(N));
}
__device__ __forceinline__ void ldsm4a(uint32_t* r, uint32_t a) {
    asm volatile("ldmatrix.sync.aligned.m8n8.x4.shared.b16 {%0,%1,%2,%3},[%4];"
                 : "=r"(r[0]), "=r"(r[1]), "=r"(r[2]), "=r"(r[3]) : "r"(a));
}
__device__ __forceinline__ void mma16816(float* c, const uint32_t* a,
                                         uint32_t b0, uint32_t b1) {
    asm volatile(
        "mma.sync.aligned.m16n8k16.row.col.f32.f16.f16.f32 "
        "{%0,%1,%2,%3},{%4,%5,%6,%7},{%8,%9},{%0,%1,%2,%3};"
        : "+f"(c[0]), "+f"(c[1]), "+f"(c[2]), "+f"(c[3])
        : "r"(a[0]), "r"(a[1]), "r"(a[2]), "r"(a[3]), "r"(b0), "r"(b1));
}
__device__ __forceinline__ float sigf(float x) { return 1.f / (1.f + expf(-x)); }

// ---------------------------------------------------------------------------
// fp16 mma.sync GEMM: C = A @ B^T + bias1 + bias2
// B fragments now loaded as ldsm4 pairs (two n8 tiles per instruction).
// ---------------------------------------------------------------------------
__global__ __launch_bounds__(256, 2)
void gemm_fp16_mma(const __half* __restrict__ A, const __half* __restrict__ B,
                   const float* __restrict__ bias1, const float* __restrict__ bias2,
                   float* __restrict__ C, int K, int ldc) {
    extern __shared__ char sm[];
    const int tid  = threadIdx.x;
    const int lane = tid & 31;
    const int wid  = tid >> 5;
    const int bm   = blockIdx.x & 31;
    const int bn   = blockIdx.x >> 5;
    const int wm   = wid >> 2;
    const int wn   = wid & 3;
    const uint32_t smb = smem_u32(sm);
    const int KT = K >> 6;

    const __half* Ag = A + (size_t)(bm * 128) * K;
    const __half* Bg = B + (size_t)(bn * 128) * K;

    auto issue = [&](int kt, int st) {
        uint32_t sa = smb + st * 32768;
#pragma unroll
        for (int j = 0; j < 8; j++) {
            int id  = tid + (j & 3) * 256;
            int row = id >> 3, c = id & 7;
            uint32_t dst = sa + (j < 4 ? 0u : 16384u)
                         + (uint32_t)(row * 128 + ((c ^ (row & 7)) << 4));
            const __half* src = (j < 4 ? Ag : Bg) + (size_t)row * K + kt * 64 + c * 8;
            cp_async16(dst, src);
        }
        cp_commit();
    };

    float acc[4][4][4];
#pragma unroll
    for (int i = 0; i < 4; i++)
#pragma unroll
        for (int j = 0; j < 4; j++)
#pragma unroll
            for (int k = 0; k < 4; k++) acc[i][j][k] = 0.f;

    issue(0, 0);
    issue(1, 1);

    const int l7  = lane & 7;
    const int l8  = (lane >> 3) & 1;
    const int l16 = lane >> 4;

    uint32_t aRow[4], bRowP[2];
#pragma unroll
    for (int mt = 0; mt < 4; mt++)
        aRow[mt] = (uint32_t)((wm * 64 + mt * 16 + l7 + l8 * 8) * 128);
#pragma unroll
    for (int ntp = 0; ntp < 2; ntp++)
        bRowP[ntp] = (uint32_t)(16384 + (wn * 32 + ntp * 16 + l16 * 8 + l7) * 128);

    for (int kt = 0; kt < KT; kt++) {
        if (kt + 1 < KT) cp_wait<1>(); else cp_wait<0>();
        __syncthreads();
        if (kt + 2 < KT) issue(kt + 2, (kt + 2) % 3);

        uint32_t st = smb + (kt % 3) * 32768;
#pragma unroll
        for (int kq = 0; kq < 4; kq++) {
            uint32_t aF[4][4], bQ[2][4];
            uint32_t ach = (uint32_t)((((kq * 2 + l16) ^ l7)) << 4);
#pragma unroll
            for (int mt = 0; mt < 4; mt++)
                ldsm4a(aF[mt], st + aRow[mt] + ach);
            uint32_t bch = (uint32_t)((((kq * 2 + l8) ^ l7)) << 4);
            ldsm4a(bQ[0], st + bRowP[0] + bch);
            ldsm4a(bQ[1], st + bRowP[1] + bch);
#pragma unroll
            for (int mt = 0; mt < 4; mt++)
#pragma unroll
                for (int nt = 0; nt < 4; nt++)
                    mma16816(acc[mt][nt], aF[mt],
                             bQ[nt >> 1][(nt & 1) * 2],
                             bQ[nt >> 1][(nt & 1) * 2 + 1]);
        }
    }

    const int gid = lane >> 2, tig = lane & 3;
#pragma unroll
    for (int mt = 0; mt < 4; mt++) {
        int row0 = bm * 128 + wm * 64 + mt * 16 + gid;
#pragma unroll
        for (int nt = 0; nt < 4; nt++) {
            int col = bn * 128 + wn * 32 + nt * 8 + tig * 2;
            float b0 = bias1 ? bias1[col] : 0.f;
            float b1 = bias1 ? bias1[col + 1] : 0.f;
            if (bias2) { b0 += bias2[col]; b1 += bias2[col + 1]; }
            *(float2*)(C + (size_t)row0 * ldc + col) =
                make_float2(acc[mt][nt][0] + b0, acc[mt][nt][1] + b1);
            *(float2*)(C + (size_t)(row0 + 8) * ldc + col) =
                make_float2(acc[mt][nt][2] + b0, acc[mt][nt][3] + b1);
        }
    }
}

// ---------------------------------------------------------------------------
// Persistent LSTM: gates = h_hi @ W_hi^T (h_lo and W_lo terms dropped)
// Block = 8 units (32 W rows), 8 h slots of k=128, 4-slot cp.async ring.
// ---------------------------------------------------------------------------
__global__ __launch_bounds__(256, 1)
void lstm_mma(const float* __restrict__ xproj,     // [T*B][4H]
              const __half* __restrict__ whh_hi,   // [4H][1024] this layer
              const float* __restrict__ c0l,       // [B][H]
              float* __restrict__ y,               // [T][B][H]
              __half* __restrict__ haug,           // [2 parity][B][H] hi
              float* __restrict__ hs_out, float* __restrict__ cs_out) {
    extern __shared__ char dsm[];
    __shared__ float sg[4][32][8];
    __shared__ unsigned s_base;

    const int tid  = threadIdx.x;
    const int blk  = blockIdx.x;
    const int n0   = blk * 8;
    const int wid  = tid >> 5;
    const int lane = tid & 31;
    const int l7   = lane & 7;
    const int l16  = lane >> 4;
    const int g2   = (lane >> 3) & 3;
    const int gid  = lane >> 2;
    const int tig  = lane & 3;
    const int mt   = wid >> 2;          // batch half
    const int nt   = wid & 3;           // gate
    const int b2   = tid >> 3;          // phase2 batch
    const int u2   = tid & 7;           // phase2 unit
    const uint32_t smb = smem_u32(dsm);
    const uint32_t HBASE = 65536;       // h slot ring base

    // load W_hi into swizzled smem chunks (16 chunks of 32 rows x 64 halves)
    for (int idx = tid; idx < 4096; idx += 256) {
        int ci  = idx >> 8;
        int rr  = (idx >> 3) & 31;
        int c   = idx & 7;
        uint32_t dst = (uint32_t)(ci * 4096 + rr * 128 + ((c ^ (rr & 7)) << 4));
        int gr = (rr >> 3) * H_ + n0 + (rr & 7);
        *(float4*)(dsm + dst) =
            *(const float4*)(whh_hi + (size_t)gr * H_ + ci * 64 + c * 8);
    }

    if (tid == 0) s_base = *(volatile unsigned*)&g_flags[blk * 32];
    float c_reg = c0l[b2 * H_ + n0 + u2];
    __syncthreads();
    const unsigned base = s_base;

    const uint32_t aRow128 = (uint32_t)((mt * 16 + l7 + ((lane >> 3) & 1) * 8) * 128);
    const uint32_t bRow128 = (uint32_t)((nt * 8 + l7) * 128);

    for (int t = 0; t < T_; ++t) {
        const int pR = t & 1, pW = (t + 1) & 1;
        const __half* hHi = haug + (size_t)pR * B_ * H_;

        // prefetch xproj gate values (independent of h)
        const float* xp = xproj + ((size_t)t * B_ + b2) * G4H + n0 + u2;
        float xpi = __ldcg(xp);
        float xpf = __ldcg(xp + H_);
        float xpg = __ldcg(xp + 2 * H_);
        float xpo = __ldcg(xp + 3 * H_);

        auto issue_slot = [&](int i) {
            int k0 = i * 128;
            uint32_t sb = smb + HBASE + (uint32_t)((i & 3) * 8192);
            int row = tid >> 3, c = tid & 7;
            uint32_t sw = (uint32_t)(row * 128 + ((c ^ (row & 7)) << 4));
#pragma unroll
            for (int cc = 0; cc < 2; cc++)
                cp_async16(sb + cc * 4096 + sw,
                           hHi + (size_t)row * H_ + k0 + cc * 64 + c * 8);
            cp_commit();
        };

        float acc[4] = {0.f, 0.f, 0.f, 0.f};

        issue_slot(0); issue_slot(1); issue_slot(2);

#pragma unroll 1
        for (int i = 0; i < 8; i++) {
            if (i < 6)       cp_wait<2>();
            else if (i == 6) cp_wait<1>();
            else             cp_wait<0>();
            __syncthreads();
            if (i + 3 < 8) issue_slot(i + 3);

            uint32_t slotB = smb + HBASE + (uint32_t)((i & 3) * 8192);
            int ciBase = i * 2;
#pragma unroll
            for (int cc = 0; cc < 2; cc++) {
                uint32_t wHi = smb + (uint32_t)((ciBase + cc) * 4096);
                uint32_t hC  = slotB + (uint32_t)(cc * 4096);
#pragma unroll
                for (int kq2 = 0; kq2 < 2; kq2++) {
                    uint32_t bOff = bRow128 + (uint32_t)((((kq2 * 4 + g2) ^ l7)) << 4);
                    uint32_t a0[4], a1[4], bh[4];
                    ldsm4a(bh, wHi + bOff);
                    ldsm4a(a0, hC + aRow128
                               + (uint32_t)((((kq2 * 4 + l16) ^ l7)) << 4));
                    ldsm4a(a1, hC + aRow128
                               + (uint32_t)((((kq2 * 4 + 2 + l16) ^ l7)) << 4));
                    mma16816(acc, a0, bh[0], bh[1]);
                    mma16816(acc, a1, bh[2], bh[3]);
                }
            }
        }

        // gates to smem: C row = batch, col = W-row (gate nt, unit tig*2)
        sg[nt][mt * 16 + gid][tig * 2]     = acc[0];
        sg[nt][mt * 16 + gid][tig * 2 + 1] = acc[1];
        sg[nt][mt * 16 + gid + 8][tig * 2]     = acc[2];
        sg[nt][mt * 16 + gid + 8][tig * 2 + 1] = acc[3];
        __syncthreads();

        // phase 2
        float gi = sg[0][b2][u2] + xpi;
        float gf = sg[1][b2][u2] + xpf;
        float gg = sg[2][b2][u2] + xpg;
        float go = sg[3][b2][u2] + xpo;
        float iv = sigf(gi), fv = sigf(gf), gv = tanhf(gg), ov = sigf(go);
        c_reg = fv * c_reg + iv * gv;
        float h = ov * tanhf(c_reg);

        y[(size_t)t * B_ * H_ + b2 * H_ + n0 + u2] = h;
        haug[(size_t)pW * B_ * H_ + b2 * H_ + n0 + u2] = __float2half_rn(h);
        if (t == T_ - 1) {
            hs_out[b2 * H_ + n0 + u2] = h;
            cs_out[b2 * H_ + n0 + u2] = c_reg;
        }

        // distributed barrier: publish own flag, all blocks poll all flags
        __syncthreads();
        unsigned tgt = base + (unsigned)(t + 1);
        if (tid == 0) {
            __threadfence();
            *(volatile unsigned*)&g_flags[blk * 32] = tgt;
        }
        if (wid == 0) {
            volatile unsigned* fl = g_flags;
            for (;;) {
                int ok = 1;
#pragma unroll
                for (int j = 0; j < 4; j++) {
                    unsigned v = fl[(lane + 32 * j) * 32];
                    if ((int)(v - tgt) < 0) ok = 0;
                }
                if (__all_sync(0xffffffffu, ok)) break;
                __nanosleep(16);
            }
            __threadfence();
        }
        __syncthreads();
    }
}

// ---------------------------------------------------------------------------
// Launch
// ---------------------------------------------------------------------------
extern "C" void kernel_launch(void* const* d_in, const int* in_sizes, int n_in,
                              void* d_out, int out_size) {
    const int*   input = (const int*)d_in[0];
    const float* h0    = (const float*)d_in[1];
    const float* c0    = (const float*)d_in[2];
    const float* emb   = (const float*)d_in[3];
    const float* W_ih  = (const float*)d_in[4];
    const float* W_hh  = (const float*)d_in[5];
    const float* b_ih  = (const float*)d_in[6];
    const float* b_hh  = (const float*)d_in[7];
    const float* dec_W = (const float*)d_in[8];
    const float* dec_b = (const float*)d_in[9];
    float* out = (float*)d_out;

    void* p;
    cudaGetSymbolAddress(&p, g_xb0);    float* xb0 = (float*)p;
    cudaGetSymbolAddress(&p, g_xb1);    float* xb1 = (float*)p;
    cudaGetSymbolAddress(&p, g_xproj);  float* xproj = (float*)p;
    cudaGetSymbolAddress(&p, g_auga);   __half* auga = (__half*)p;
    cudaGetSymbolAddress(&p, g_augwih); __half* augwih = (__half*)p;
    cudaGetSymbolAddress(&p, g_augdec); __half* augdec = (__half*)p;
    cudaGetSymbolAddress(&p, g_whhaug); __half* whhaug = (__half*)p;
    cudaGetSymbolAddress(&p, g_haug);   __half* haug = (__half*)p;

    cudaFuncSetAttribute(gemm_fp16_mma,
                         cudaFuncAttributeMaxDynamicSharedMemorySize, GEMM_SMEM);
    cudaFuncSetAttribute(lstm_mma,
                         cudaFuncAttributeMaxDynamicSharedMemorySize, LSTM_SMEM);

    // 1) embedding + weight augmentations
    embed_kernel<<<TB, 256>>>(input, emb, xb0);
    augh_kernel<<<V_, 256>>>(dec_W, augdec, 1);                      // [hi|hi]
    augh_kernel<<<G4H, 256>>>(W_ih, augwih, 1);                      // [hi|hi]
    augh_kernel<<<G4H, 256>>>(W_ih + (size_t)G4H * E_,
                              augwih + (size_t)G4H * K2, 1);
    whh_aug_kernel<<<L_ * G4H, 256>>>(W_hh, whhaug);

    const size_t D0 = (size_t)TB * V_;
    const size_t BH = (size_t)B_ * H_;

    for (int l = 0; l < L_; ++l) {
        const float* xin = l ? xb1 : xb0;
        float*       y   = l ? xb0 : xb1;

        // 2) activation augmentation + fp16 tensor-core input projection
        augh_kernel<<<TB, 256>>>(xin, auga, 0);                      // [hi|lo]
        gemm_fp16_mma<<<(G4H / 128) * 32, 256, GEMM_SMEM>>>(
            auga, augwih + (size_t)l * G4H * K2,
            b_ih + (size_t)l * G4H, b_hh + (size_t)l * G4H,
            xproj, K2, G4H);

        // 3) recurrence (persistent, mma.sync)
        h0_aug_kernel<<<B_, 256>>>(h0 + (size_t)l * BH, haug);       // parity 0
        lstm_mma<<<NBLK, 256, LSTM_SMEM>>>(
            xproj, whhaug + (size_t)l * G4H * H_,
            c0 + (size_t)l * BH, y, haug,
            out + D0 + (size_t)l * BH,
            out + D0 + (size_t)L_ * BH + (size_t)l * BH);
    }

    // 4) decoder: 2-term fp16 split
    augh_kernel<<<TB, 256>>>(xb0, auga, 0);                          // [hi|lo]
    gemm_fp16_mma<<<(V_ / 128) * 32, 256, GEMM_SMEM>>>(
        auga, augdec, dec_b, nullptr, out, K2, V_);
}